// round 3
// baseline (speedup 1.0000x reference)
#include <cuda_runtime.h>
#include <cstdint>

// Problem constants
#define TT 16384   // B*S tokens
#define HH 1024    // hidden
#define II 4096    // intermediate
#define EE 8       // experts

// ---------------- scratch (device globals; no runtime allocation) ----------
__device__ int   d_counts[EE];
__device__ int   d_offsets[EE];
__device__ int   d_tok[EE * TT];
__device__ float d_wt[EE * TT];
// Compact per-(expert,token) intermediate activations (tf32-pre-rounded).
__device__ float d_hmid[(size_t)2 * TT * II];   // 536 MB

// ---------------- helpers ----------------
__device__ __forceinline__ uint32_t f2tf32(float f) {
    uint32_t r;
    asm("cvt.rna.tf32.f32 %0, %1;" : "=r"(r) : "f"(f));
    return r;
}
__device__ __forceinline__ float silu_f(float v) {
    return v / (1.0f + __expf(-v));
}

#define MMA_TF32(D, A, B_)                                                       \
    asm volatile(                                                                \
        "mma.sync.aligned.m16n8k8.row.col.f32.tf32.tf32.f32 "                    \
        "{%0,%1,%2,%3}, {%4,%5,%6,%7}, {%8,%9}, {%0,%1,%2,%3};\n"                \
        : "+f"((D)[0]), "+f"((D)[1]), "+f"((D)[2]), "+f"((D)[3])                 \
        : "r"((A)[0]), "r"((A)[1]), "r"((A)[2]), "r"((A)[3]),                    \
          "r"((B_)[0]), "r"((B_)[1]))

// ---------------- kernel 0: zero per-expert counters ----------------
__global__ void init_counts_kernel() {
    if (threadIdx.x < EE) d_counts[threadIdx.x] = 0;
}

// ---------------- kernel 1: router ----------------
__global__ __launch_bounds__(256)
void router_kernel(const float* __restrict__ x,
                   const float* __restrict__ Wg,
                   float* __restrict__ logits_out) {
    __shared__ float sWg[EE][HH];   // 32 KB
    for (int i = threadIdx.x; i < EE * HH; i += blockDim.x)
        sWg[i / HH][i % HH] = Wg[i];
    __syncthreads();

    const int warp = threadIdx.x >> 5;
    const int lane = threadIdx.x & 31;
    const int t = blockIdx.x * 8 + warp;
    if (t >= TT) return;

    const float* xr = x + (size_t)t * HH;
    float acc[EE];
#pragma unroll
    for (int e = 0; e < EE; e++) acc[e] = 0.0f;

    for (int k = lane; k < HH; k += 32) {
        float xv = xr[k];
#pragma unroll
        for (int e = 0; e < EE; e++) acc[e] += xv * sWg[e][k];
    }
#pragma unroll
    for (int off = 16; off > 0; off >>= 1) {
#pragma unroll
        for (int e = 0; e < EE; e++)
            acc[e] += __shfl_xor_sync(0xFFFFFFFFu, acc[e], off);
    }

    if (lane == 0) {
        if (logits_out) {
#pragma unroll
            for (int e = 0; e < EE; e++) logits_out[(size_t)t * EE + e] = acc[e];
        }
        int i0 = 0; float v0 = acc[0];
#pragma unroll
        for (int e = 1; e < EE; e++) if (acc[e] > v0) { v0 = acc[e]; i0 = e; }
        int i1 = -1; float v1 = -3.4e38f;
#pragma unroll
        for (int e = 0; e < EE; e++)
            if (e != i0 && acc[e] > v1) { v1 = acc[e]; i1 = e; }
        float r  = expf(v1 - v0);
        float w0 = 1.0f / (1.0f + r);
        float w1 = 1.0f - w0;

        int p0 = atomicAdd(&d_counts[i0], 1);
        d_tok[i0 * TT + p0] = t;  d_wt[i0 * TT + p0] = w0;
        int p1 = atomicAdd(&d_counts[i1], 1);
        d_tok[i1 * TT + p1] = t;  d_wt[i1 * TT + p1] = w1;
    }
}

// ---------------- kernel 2: prefix scan over 8 counts ----------------
__global__ void scan_kernel() {
    int off = 0;
#pragma unroll
    for (int e = 0; e < EE; e++) { d_offsets[e] = off; off += d_counts[e]; }
}

// ---------------- kernels 3/4: tiled tf32 mma GEMM, 128x256 CTA ----------
// 8 warps, 64x64 per warp (2 m-warps x 4 n-warps).
// FIRST  : hmid[r] = tf32(silu(x[tok(r)] @ W1e^T + b1e))   (K = H = 1024)
// !FIRST : out[tok(r)] += w(r) * (hmid[r] @ W2e^T + b2e)   (K = I = 4096)
constexpr int BM = 128, BN = 256, BK = 16, BKP = 20;

template <bool FIRST>
__global__ __launch_bounds__(256, 1)
void moe_gemm_kernel(const float* __restrict__ X,
                     const float* __restrict__ W,
                     const float* __restrict__ bias,
                     float* __restrict__ out) {
    const int e   = blockIdx.z;
    const int cnt = d_counts[e];
    const int m0  = blockIdx.y * BM;
    if (m0 >= cnt) return;
    const int n0   = blockIdx.x * BN;
    const int KDIM = FIRST ? HH : II;
    const int NDIM = FIRST ? II : HH;
    const int offs = d_offsets[e];

    __shared__ uint32_t As[BM][BKP];   // 10 KB
    __shared__ uint32_t Bs[BN][BKP];   // 20 KB

    const int tid = threadIdx.x;

    // loaders: A = 2 float4/thread (128x16), B = 4 float4/thread (256x16)
    const float* aPtr[2]; int arL[2], acL[2];
#pragma unroll
    for (int j = 0; j < 2; j++) {
        int idx = tid + j * 256;
        int row = idx >> 2, col = (idx & 3) * 4;
        arL[j] = row; acL[j] = col;
        int gm = m0 + row;
        if (gm >= cnt) gm = cnt - 1;
        if (FIRST) {
            int tok = d_tok[e * TT + gm];
            aPtr[j] = X + (size_t)tok * HH + col;
        } else {
            aPtr[j] = d_hmid + (size_t)(offs + gm) * II + col;
        }
    }
    const float* bPtr[4]; int brL[4], bcL[4];
#pragma unroll
    for (int j = 0; j < 4; j++) {
        int idx = tid + j * 256;
        int row = idx >> 2, col = (idx & 3) * 4;
        brL[j] = row; bcL[j] = col;
        bPtr[j] = W + (size_t)e * ((size_t)II * HH) + (size_t)(n0 + row) * KDIM + col;
    }

    float4 va[2], vb[4];
#pragma unroll
    for (int j = 0; j < 2; j++) va[j] = *(const float4*)(aPtr[j]);
#pragma unroll
    for (int j = 0; j < 4; j++) vb[j] = *(const float4*)(bPtr[j]);

    const int wid = tid >> 5, lane = tid & 31;
    const int wm = (wid & 1) * 64;        // 0 or 64
    const int wn = (wid >> 1) * 64;       // 0,64,128,192
    const int g = lane >> 2, tg = lane & 3;

    float acc[4][8][4];
#pragma unroll
    for (int a = 0; a < 4; a++)
#pragma unroll
        for (int b = 0; b < 8; b++)
#pragma unroll
            for (int c = 0; c < 4; c++) acc[a][b][c] = 0.0f;

    for (int k0 = 0; k0 < KDIM; k0 += BK) {
        // store current tile to smem (A: cvt only for GEMM1; hmid is pre-rounded)
#pragma unroll
        for (int j = 0; j < 2; j++) {
            uint32_t* dA = &As[arL[j]][acL[j]];
            if (FIRST) {
                dA[0] = f2tf32(va[j].x); dA[1] = f2tf32(va[j].y);
                dA[2] = f2tf32(va[j].z); dA[3] = f2tf32(va[j].w);
            } else {
                dA[0] = __float_as_uint(va[j].x); dA[1] = __float_as_uint(va[j].y);
                dA[2] = __float_as_uint(va[j].z); dA[3] = __float_as_uint(va[j].w);
            }
        }
#pragma unroll
        for (int j = 0; j < 4; j++) {
            uint32_t* dB = &Bs[brL[j]][bcL[j]];
            dB[0] = f2tf32(vb[j].x); dB[1] = f2tf32(vb[j].y);
            dB[2] = f2tf32(vb[j].z); dB[3] = f2tf32(vb[j].w);
        }
        __syncthreads();

        if (k0 + BK < KDIM) {   // register prefetch of next tile
#pragma unroll
            for (int j = 0; j < 2; j++) va[j] = *(const float4*)(aPtr[j] + k0 + BK);
#pragma unroll
            for (int j = 0; j < 4; j++) vb[j] = *(const float4*)(bPtr[j] + k0 + BK);
        }

#pragma unroll
        for (int kk = 0; kk < BK; kk += 8) {
            uint32_t af[4][4], bf[8][2];
#pragma unroll
            for (int mf = 0; mf < 4; mf++) {
                int m = wm + mf * 16 + g;
                af[mf][0] = As[m][kk + tg];
                af[mf][1] = As[m + 8][kk + tg];
                af[mf][2] = As[m][kk + tg + 4];
                af[mf][3] = As[m + 8][kk + tg + 4];
            }
#pragma unroll
            for (int nf = 0; nf < 8; nf++) {
                int n = wn + nf * 8 + g;
                bf[nf][0] = Bs[n][kk + tg];
                bf[nf][1] = Bs[n][kk + tg + 4];
            }
#pragma unroll
            for (int mf = 0; mf < 4; mf++)
#pragma unroll
                for (int nf = 0; nf < 8; nf++)
                    MMA_TF32(acc[mf][nf], af[mf], bf[nf]);
        }
        __syncthreads();
    }

    // epilogue
#pragma unroll
    for (int mf = 0; mf < 4; mf++) {
#pragma unroll
        for (int half = 0; half < 2; half++) {
            int m = m0 + wm + mf * 16 + g + half * 8;
            if (m >= cnt) continue;
            if (FIRST) {
                float* dst = d_hmid + (size_t)(offs + m) * II + n0;
#pragma unroll
                for (int nf = 0; nf < 8; nf++) {
                    int col = wn + nf * 8 + tg * 2;
                    float bb0 = bias[(size_t)e * NDIM + n0 + col];
                    float bb1 = bias[(size_t)e * NDIM + n0 + col + 1];
                    float s0 = __uint_as_float(f2tf32(silu_f(acc[mf][nf][half * 2 + 0] + bb0)));
                    float s1 = __uint_as_float(f2tf32(silu_f(acc[mf][nf][half * 2 + 1] + bb1)));
                    *(float2*)(dst + col) = make_float2(s0, s1);
                }
            } else {
                int tok = d_tok[e * TT + m];
                float w = d_wt[e * TT + m];
                float* dst = out + (size_t)tok * HH + n0;
#pragma unroll
                for (int nf = 0; nf < 8; nf++) {
                    int col = wn + nf * 8 + tg * 2;
                    float bb0 = bias[(size_t)e * NDIM + n0 + col];
                    float bb1 = bias[(size_t)e * NDIM + n0 + col + 1];
                    atomicAdd(dst + col,     w * (acc[mf][nf][half * 2 + 0] + bb0));
                    atomicAdd(dst + col + 1, w * (acc[mf][nf][half * 2 + 1] + bb1));
                }
            }
        }
    }
}

// ---------------- launch ----------------
extern "C" void kernel_launch(void* const* d_in, const int* in_sizes, int n_in,
                              void* d_out, int out_size) {
    const float* x  = (const float*)d_in[0];   // [T,H]
    const float* Wg = (const float*)d_in[1];   // [E,H]
    const float* W1 = (const float*)d_in[2];   // [E,I,H]
    const float* b1 = (const float*)d_in[3];   // [E,I]
    const float* W2 = (const float*)d_in[4];   // [E,H,I]
    const float* b2 = (const float*)d_in[5];   // [E,H]
    float* out = (float*)d_out;

    float* logits = nullptr;
    if ((size_t)out_size >= (size_t)TT * HH + (size_t)TT * EE)
        logits = out + (size_t)TT * HH;

    init_counts_kernel<<<1, 32>>>();
    router_kernel<<<TT / 8, 256>>>(x, Wg, logits);
    scan_kernel<<<1, 1>>>();
    cudaMemsetAsync(out, 0, (size_t)TT * HH * sizeof(float), 0);

    dim3 g1(II / BN, TT / BM, EE);   // (16, 128, 8)
    moe_gemm_kernel<true><<<g1, 256>>>(x, W1, b1, nullptr);

    dim3 g2(HH / BN, TT / BM, EE);   // (4, 128, 8)
    moe_gemm_kernel<false><<<g2, 256>>>(nullptr, W2, b2, out);
}

// round 4
// speedup vs baseline: 1.1171x; 1.1171x over previous
#include <cuda_runtime.h>
#include <cstdint>

// Problem constants
#define TT 16384   // B*S tokens
#define HH 1024    // hidden
#define II 4096    // intermediate
#define EE 8       // experts

// ---------------- scratch (device globals; no runtime allocation) ----------
__device__ int   d_counts[EE];
__device__ int   d_offsets[EE];
__device__ int   d_tok[EE * TT];
__device__ float d_wt[EE * TT];
__device__ float d_hmid[(size_t)2 * TT * II];   // 536 MB, tf32-pre-rounded
__device__ float d_xt[(size_t)TT * HH];         // tf32-rounded x
__device__ float d_w1t[(size_t)EE * II * HH];   // tf32-rounded W1
__device__ float d_w2t[(size_t)EE * HH * II];   // tf32-rounded W2

// ---------------- helpers ----------------
__device__ __forceinline__ uint32_t f2tf32(float f) {
    uint32_t r;
    asm("cvt.rna.tf32.f32 %0, %1;" : "=r"(r) : "f"(f));
    return r;
}
__device__ __forceinline__ float silu_f(float v) { return v / (1.0f + __expf(-v)); }
__device__ __forceinline__ uint32_t smem_u32(const void* p) {
    uint32_t a;
    asm("{ .reg .u64 t; cvta.to.shared.u64 t, %1; cvt.u32.u64 %0, t; }" : "=r"(a) : "l"(p));
    return a;
}

#define MMA_TF32(D, A, B_)                                                       \
    asm volatile(                                                                \
        "mma.sync.aligned.m16n8k8.row.col.f32.tf32.tf32.f32 "                    \
        "{%0,%1,%2,%3}, {%4,%5,%6,%7}, {%8,%9}, {%0,%1,%2,%3};\n"                \
        : "+f"((D)[0]), "+f"((D)[1]), "+f"((D)[2]), "+f"((D)[3])                 \
        : "r"((A)[0]), "r"((A)[1]), "r"((A)[2]), "r"((A)[3]),                    \
          "r"((B_)[0]), "r"((B_)[1]))

#define CP_ASYNC16(saddr, gptr) \
    asm volatile("cp.async.cg.shared.global [%0], [%1], 16;" :: "r"(saddr), "l"(gptr) : "memory")
#define CP_COMMIT() asm volatile("cp.async.commit_group;" ::: "memory")
#define CP_WAIT1()  asm volatile("cp.async.wait_group 1;" ::: "memory")

// ---------------- kernel: tf32-rna pre-rounding copy ----------------
__global__ __launch_bounds__(256)
void cvt_tf32_kernel(const float4* __restrict__ src, int which, size_t n4) {
    float4* dst = (which == 0) ? (float4*)d_xt : (which == 1) ? (float4*)d_w1t : (float4*)d_w2t;
    size_t i  = (size_t)blockIdx.x * blockDim.x + threadIdx.x;
    size_t st = (size_t)gridDim.x * blockDim.x;
    for (; i < n4; i += st) {
        float4 v = src[i];
        float4 o;
        o.x = __uint_as_float(f2tf32(v.x));
        o.y = __uint_as_float(f2tf32(v.y));
        o.z = __uint_as_float(f2tf32(v.z));
        o.w = __uint_as_float(f2tf32(v.w));
        dst[i] = o;
    }
}

// ---------------- kernel 0: zero per-expert counters ----------------
__global__ void init_counts_kernel() {
    if (threadIdx.x < EE) d_counts[threadIdx.x] = 0;
}

// ---------------- kernel 1: router ----------------
__global__ __launch_bounds__(256)
void router_kernel(const float* __restrict__ x,
                   const float* __restrict__ Wg,
                   float* __restrict__ logits_out) {
    __shared__ float sWg[EE][HH];
    for (int i = threadIdx.x; i < EE * HH; i += blockDim.x)
        sWg[i / HH][i % HH] = Wg[i];
    __syncthreads();

    const int warp = threadIdx.x >> 5;
    const int lane = threadIdx.x & 31;
    const int t = blockIdx.x * 8 + warp;
    if (t >= TT) return;

    const float* xr = x + (size_t)t * HH;
    float acc[EE];
#pragma unroll
    for (int e = 0; e < EE; e++) acc[e] = 0.0f;
    for (int k = lane; k < HH; k += 32) {
        float xv = xr[k];
#pragma unroll
        for (int e = 0; e < EE; e++) acc[e] += xv * sWg[e][k];
    }
#pragma unroll
    for (int off = 16; off > 0; off >>= 1)
#pragma unroll
        for (int e = 0; e < EE; e++)
            acc[e] += __shfl_xor_sync(0xFFFFFFFFu, acc[e], off);

    if (lane == 0) {
        if (logits_out)
#pragma unroll
            for (int e = 0; e < EE; e++) logits_out[(size_t)t * EE + e] = acc[e];
        int i0 = 0; float v0 = acc[0];
#pragma unroll
        for (int e = 1; e < EE; e++) if (acc[e] > v0) { v0 = acc[e]; i0 = e; }
        int i1 = -1; float v1 = -3.4e38f;
#pragma unroll
        for (int e = 0; e < EE; e++)
            if (e != i0 && acc[e] > v1) { v1 = acc[e]; i1 = e; }
        float r  = expf(v1 - v0);
        float w0 = 1.0f / (1.0f + r);
        float w1 = 1.0f - w0;
        int p0 = atomicAdd(&d_counts[i0], 1);
        d_tok[i0 * TT + p0] = t;  d_wt[i0 * TT + p0] = w0;
        int p1 = atomicAdd(&d_counts[i1], 1);
        d_tok[i1 * TT + p1] = t;  d_wt[i1 * TT + p1] = w1;
    }
}

// ---------------- kernel 2: prefix scan ----------------
__global__ void scan_kernel() {
    int off = 0;
#pragma unroll
    for (int e = 0; e < EE; e++) { d_offsets[e] = off; off += d_counts[e]; }
}

// ---------------- GEMM: 128x256 CTA, 8 warps 64x64, 3-stage cp.async -----
// All operands pre-rounded tf32 fp32; no cvt in mainloop.
constexpr int BM = 128, BN = 256, BK = 16, BKP = 20;     // 20-word padded rows
constexpr int A_STAGE_B = BM * BKP * 4;                  // 10240 B
constexpr int B_STAGE_B = BN * BKP * 4;                  // 20480 B
constexpr int STAGE_B   = A_STAGE_B + B_STAGE_B;         // 30720 B
constexpr int NSTAGE    = 3;
constexpr int SMEM_DYN  = NSTAGE * STAGE_B;              // 92160 B

template <bool FIRST>
__global__ __launch_bounds__(256, 1)
void moe_gemm_kernel(const float* __restrict__ bias, float* __restrict__ out) {
    const int e   = blockIdx.z;
    const int cnt = d_counts[e];
    const int m0  = blockIdx.y * BM;
    if (m0 >= cnt) return;
    const int n0   = blockIdx.x * BN;
    const int KDIM = FIRST ? HH : II;
    const int NDIM = FIRST ? II : HH;
    const int offs = d_offsets[e];
    const int NC   = KDIM / BK;

    extern __shared__ char dynsmem[];
    const uint32_t sbase = smem_u32(dynsmem);

    const int tid = threadIdx.x;
    const float* Aglob = FIRST ? d_xt : d_hmid;
    const float* Wt    = FIRST ? d_w1t : d_w2t;

    // A: 2 16B-chunks/thread (128x16), B: 4 chunks/thread (256x16)
    const float* aG[2]; uint32_t aSoff[2];
#pragma unroll
    for (int j = 0; j < 2; j++) {
        int idx = tid + j * 256;
        int row = idx >> 2, c = idx & 3;
        int gm = m0 + row;
        if (gm >= cnt) gm = cnt - 1;
        size_t rowoff;
        if (FIRST) rowoff = (size_t)d_tok[e * TT + gm] * HH;
        else       rowoff = (size_t)(offs + gm) * II;
        aG[j]    = Aglob + rowoff + c * 4;
        aSoff[j] = row * (BKP * 4) + c * 16;
    }
    const float* bG[4]; uint32_t bSoff[4];
#pragma unroll
    for (int j = 0; j < 4; j++) {
        int idx = tid + j * 256;
        int row = idx >> 2, c = idx & 3;
        bG[j]    = Wt + (size_t)e * ((size_t)II * HH) + (size_t)(n0 + row) * KDIM + c * 4;
        bSoff[j] = A_STAGE_B + row * (BKP * 4) + c * 16;
    }

    // prologue: stages 0,1
#pragma unroll
    for (int s = 0; s < NSTAGE - 1; s++) {
        uint32_t so = sbase + s * STAGE_B;
#pragma unroll
        for (int j = 0; j < 2; j++) CP_ASYNC16(so + aSoff[j], aG[j] + s * BK);
#pragma unroll
        for (int j = 0; j < 4; j++) CP_ASYNC16(so + bSoff[j], bG[j] + s * BK);
        CP_COMMIT();
    }

    const int wid = tid >> 5, lane = tid & 31;
    const int wm = (wid & 1) * 64;
    const int wn = (wid >> 1) * 64;
    const int g = lane >> 2, tg = lane & 3;

    float acc[4][8][4];
#pragma unroll
    for (int a = 0; a < 4; a++)
#pragma unroll
        for (int b = 0; b < 8; b++)
#pragma unroll
            for (int c = 0; c < 4; c++) acc[a][b][c] = 0.0f;

    int stage = 0;
    for (int i = 0; i < NC; i++) {
        CP_WAIT1();
        __syncthreads();

        // issue load for chunk i+2 into the buffer freed by compute(i-1)
        const int nx = i + NSTAGE - 1;
        if (nx < NC) {
            int s = nx % NSTAGE;
            uint32_t so = sbase + s * STAGE_B;
#pragma unroll
            for (int j = 0; j < 2; j++) CP_ASYNC16(so + aSoff[j], aG[j] + nx * BK);
#pragma unroll
            for (int j = 0; j < 4; j++) CP_ASYNC16(so + bSoff[j], bG[j] + nx * BK);
        }
        CP_COMMIT();

        const uint32_t* As = (const uint32_t*)(dynsmem + stage * STAGE_B);
        const uint32_t* Bs = (const uint32_t*)(dynsmem + stage * STAGE_B + A_STAGE_B);

#pragma unroll
        for (int kk = 0; kk < BK; kk += 8) {
            uint32_t af[4][4], bf[8][2];
#pragma unroll
            for (int mf = 0; mf < 4; mf++) {
                int m = wm + mf * 16 + g;
                af[mf][0] = As[m * BKP + kk + tg];
                af[mf][1] = As[(m + 8) * BKP + kk + tg];
                af[mf][2] = As[m * BKP + kk + tg + 4];
                af[mf][3] = As[(m + 8) * BKP + kk + tg + 4];
            }
#pragma unroll
            for (int nf = 0; nf < 8; nf++) {
                int n = wn + nf * 8 + g;
                bf[nf][0] = Bs[n * BKP + kk + tg];
                bf[nf][1] = Bs[n * BKP + kk + tg + 4];
            }
#pragma unroll
            for (int mf = 0; mf < 4; mf++)
#pragma unroll
                for (int nf = 0; nf < 8; nf++)
                    MMA_TF32(acc[mf][nf], af[mf], bf[nf]);
        }
        stage = (stage + 1 == NSTAGE) ? 0 : stage + 1;
    }

    // epilogue
#pragma unroll
    for (int mf = 0; mf < 4; mf++) {
#pragma unroll
        for (int half = 0; half < 2; half++) {
            int m = m0 + wm + mf * 16 + g + half * 8;
            if (m >= cnt) continue;
            if (FIRST) {
                float* dst = d_hmid + (size_t)(offs + m) * II + n0;
#pragma unroll
                for (int nf = 0; nf < 8; nf++) {
                    int col = wn + nf * 8 + tg * 2;
                    float bb0 = bias[(size_t)e * NDIM + n0 + col];
                    float bb1 = bias[(size_t)e * NDIM + n0 + col + 1];
                    float s0 = __uint_as_float(f2tf32(silu_f(acc[mf][nf][half * 2 + 0] + bb0)));
                    float s1 = __uint_as_float(f2tf32(silu_f(acc[mf][nf][half * 2 + 1] + bb1)));
                    *(float2*)(dst + col) = make_float2(s0, s1);
                }
            } else {
                int tok = d_tok[e * TT + m];
                float w = d_wt[e * TT + m];
                float* dst = out + (size_t)tok * HH + n0;
#pragma unroll
                for (int nf = 0; nf < 8; nf++) {
                    int col = wn + nf * 8 + tg * 2;
                    float bb0 = bias[(size_t)e * NDIM + n0 + col];
                    float bb1 = bias[(size_t)e * NDIM + n0 + col + 1];
                    atomicAdd(dst + col,     w * (acc[mf][nf][half * 2 + 0] + bb0));
                    atomicAdd(dst + col + 1, w * (acc[mf][nf][half * 2 + 1] + bb1));
                }
            }
        }
    }
}

// ---------------- launch ----------------
extern "C" void kernel_launch(void* const* d_in, const int* in_sizes, int n_in,
                              void* d_out, int out_size) {
    const float* x  = (const float*)d_in[0];   // [T,H]
    const float* Wg = (const float*)d_in[1];   // [E,H]
    const float* W1 = (const float*)d_in[2];   // [E,I,H]
    const float* b1 = (const float*)d_in[3];   // [E,I]
    const float* W2 = (const float*)d_in[4];   // [E,H,I]
    const float* b2 = (const float*)d_in[5];   // [E,H]
    float* out = (float*)d_out;

    float* logits = nullptr;
    if ((size_t)out_size >= (size_t)TT * HH + (size_t)TT * EE)
        logits = out + (size_t)TT * HH;

    cudaFuncSetAttribute(moe_gemm_kernel<true>,  cudaFuncAttributeMaxDynamicSharedMemorySize, SMEM_DYN);
    cudaFuncSetAttribute(moe_gemm_kernel<false>, cudaFuncAttributeMaxDynamicSharedMemorySize, SMEM_DYN);

    init_counts_kernel<<<1, 32>>>();
    router_kernel<<<TT / 8, 256>>>(x, Wg, logits);
    scan_kernel<<<1, 1>>>();
    cudaMemsetAsync(out, 0, (size_t)TT * HH * sizeof(float), 0);

    cvt_tf32_kernel<<<2048, 256>>>((const float4*)x,  0, (size_t)TT * HH / 4);
    cvt_tf32_kernel<<<2048, 256>>>((const float4*)W1, 1, (size_t)EE * II * HH / 4);
    cvt_tf32_kernel<<<2048, 256>>>((const float4*)W2, 2, (size_t)EE * HH * II / 4);

    dim3 g1(II / BN, TT / BM, EE);   // (16, 128, 8)
    moe_gemm_kernel<true><<<g1, 256, SMEM_DYN>>>(b1, nullptr);

    dim3 g2(HH / BN, TT / BM, EE);   // (4, 128, 8)
    moe_gemm_kernel<false><<<g2, 256, SMEM_DYN>>>(b2, out);
}

// round 5
// speedup vs baseline: 2.0012x; 1.7915x over previous
#include <cuda_runtime.h>
#include <cuda_fp16.h>
#include <cstdint>

// Problem constants
#define TT 16384   // B*S tokens
#define HH 1024    // hidden
#define II 4096    // intermediate
#define EE 8       // experts

// ---------------- scratch (device globals; no runtime allocation) ----------
__device__ int    d_counts[EE];
__device__ int    d_offsets[EE];
__device__ int    d_tok[EE * TT];
__device__ float  d_wt[EE * TT];
__device__ __half d_hmid[(size_t)2 * TT * II];    // fp16 intermediate (268 MB)
__device__ __half d_xh[(size_t)TT * HH];          // fp16 x
__device__ __half d_w1h[(size_t)EE * II * HH];    // fp16 W1
__device__ __half d_w2h[(size_t)EE * HH * II];    // fp16 W2

// ---------------- helpers ----------------
__device__ __forceinline__ float silu_f(float v) { return v / (1.0f + __expf(-v)); }
__device__ __forceinline__ uint32_t smem_u32(const void* p) {
    uint32_t a;
    asm("{ .reg .u64 t; cvta.to.shared.u64 t, %1; cvt.u32.u64 %0, t; }" : "=r"(a) : "l"(p));
    return a;
}

#define MMA_F16(D, A, B_)                                                        \
    asm volatile(                                                                \
        "mma.sync.aligned.m16n8k16.row.col.f32.f16.f16.f32 "                     \
        "{%0,%1,%2,%3}, {%4,%5,%6,%7}, {%8,%9}, {%0,%1,%2,%3};\n"                \
        : "+f"((D)[0]), "+f"((D)[1]), "+f"((D)[2]), "+f"((D)[3])                 \
        : "r"((A)[0]), "r"((A)[1]), "r"((A)[2]), "r"((A)[3]),                    \
          "r"((B_)[0]), "r"((B_)[1]))

#define CP_ASYNC16(saddr, gptr) \
    asm volatile("cp.async.cg.shared.global [%0], [%1], 16;" :: "r"(saddr), "l"(gptr) : "memory")
#define CP_COMMIT() asm volatile("cp.async.commit_group;" ::: "memory")
#define CP_WAIT1()  asm volatile("cp.async.wait_group 1;" ::: "memory")

// ---------------- kernel: fp32 -> fp16 conversion pass ----------------
__global__ __launch_bounds__(256)
void cvt_f16_kernel(const float4* __restrict__ src, int which, size_t n4) {
    __half* dstb = (which == 0) ? d_xh : (which == 1) ? d_w1h : d_w2h;
    uint2* dst = (uint2*)dstb;
    size_t i  = (size_t)blockIdx.x * blockDim.x + threadIdx.x;
    size_t st = (size_t)gridDim.x * blockDim.x;
    for (; i < n4; i += st) {
        float4 v = src[i];
        __half2 h0 = __floats2half2_rn(v.x, v.y);
        __half2 h1 = __floats2half2_rn(v.z, v.w);
        uint2 o;
        o.x = *(uint32_t*)&h0;
        o.y = *(uint32_t*)&h1;
        dst[i] = o;
    }
}

// ---------------- kernel 0: zero per-expert counters ----------------
__global__ void init_counts_kernel() {
    if (threadIdx.x < EE) d_counts[threadIdx.x] = 0;
}

// ---------------- kernel 1: router (fp32, unchanged) ----------------
__global__ __launch_bounds__(256)
void router_kernel(const float* __restrict__ x,
                   const float* __restrict__ Wg,
                   float* __restrict__ logits_out) {
    __shared__ float sWg[EE][HH];
    for (int i = threadIdx.x; i < EE * HH; i += blockDim.x)
        sWg[i / HH][i % HH] = Wg[i];
    __syncthreads();

    const int warp = threadIdx.x >> 5;
    const int lane = threadIdx.x & 31;
    const int t = blockIdx.x * 8 + warp;
    if (t >= TT) return;

    const float* xr = x + (size_t)t * HH;
    float acc[EE];
#pragma unroll
    for (int e = 0; e < EE; e++) acc[e] = 0.0f;
    for (int k = lane; k < HH; k += 32) {
        float xv = xr[k];
#pragma unroll
        for (int e = 0; e < EE; e++) acc[e] += xv * sWg[e][k];
    }
#pragma unroll
    for (int off = 16; off > 0; off >>= 1)
#pragma unroll
        for (int e = 0; e < EE; e++)
            acc[e] += __shfl_xor_sync(0xFFFFFFFFu, acc[e], off);

    if (lane == 0) {
        if (logits_out)
#pragma unroll
            for (int e = 0; e < EE; e++) logits_out[(size_t)t * EE + e] = acc[e];
        int i0 = 0; float v0 = acc[0];
#pragma unroll
        for (int e = 1; e < EE; e++) if (acc[e] > v0) { v0 = acc[e]; i0 = e; }
        int i1 = -1; float v1 = -3.4e38f;
#pragma unroll
        for (int e = 0; e < EE; e++)
            if (e != i0 && acc[e] > v1) { v1 = acc[e]; i1 = e; }
        float r  = expf(v1 - v0);
        float w0 = 1.0f / (1.0f + r);
        float w1 = 1.0f - w0;
        int p0 = atomicAdd(&d_counts[i0], 1);
        d_tok[i0 * TT + p0] = t;  d_wt[i0 * TT + p0] = w0;
        int p1 = atomicAdd(&d_counts[i1], 1);
        d_tok[i1 * TT + p1] = t;  d_wt[i1 * TT + p1] = w1;
    }
}

// ---------------- kernel 2: prefix scan ----------------
__global__ void scan_kernel() {
    int off = 0;
#pragma unroll
    for (int e = 0; e < EE; e++) { d_offsets[e] = off; off += d_counts[e]; }
}

// ---------------- GEMM: fp16 m16n8k16, 128x256 CTA, BK=32, 3-stage ------
// 8 warps, 64x64 per warp. All operands fp16, fp32 accumulate.
constexpr int BM = 128, BN = 256, BK = 32;
constexpr int BKW = 20;                            // padded words/row (16 data + 4 pad)
constexpr int A_STAGE_B = BM * BKW * 4;            // 10240 B
constexpr int B_STAGE_B = BN * BKW * 4;            // 20480 B
constexpr int STAGE_B   = A_STAGE_B + B_STAGE_B;   // 30720 B
constexpr int NSTAGE    = 3;
constexpr int SMEM_DYN  = NSTAGE * STAGE_B;        // 92160 B

template <bool FIRST>
__global__ __launch_bounds__(256, 1)
void moe_gemm_kernel(const float* __restrict__ bias, float* __restrict__ out) {
    const int e   = blockIdx.z;
    const int cnt = d_counts[e];
    const int m0  = blockIdx.y * BM;
    if (m0 >= cnt) return;
    const int n0   = blockIdx.x * BN;
    const int KDIM = FIRST ? HH : II;
    const int NDIM = FIRST ? II : HH;
    const int offs = d_offsets[e];
    const int NC   = KDIM / BK;

    extern __shared__ char dynsmem[];
    const uint32_t sbase = smem_u32(dynsmem);

    const int tid = threadIdx.x;
    const __half* Aglob = FIRST ? d_xh : d_hmid;
    const __half* Wt    = FIRST ? d_w1h : d_w2h;

    // A: 128 rows x 32 halves (64B) = 4 x16B chunks/row -> 2 chunks/thread
    // B: 256 rows x 64B = 4 chunks/row -> 4 chunks/thread
    const __half* aG[2]; uint32_t aSoff[2];
#pragma unroll
    for (int j = 0; j < 2; j++) {
        int idx = tid + j * 256;
        int row = idx >> 2, c = idx & 3;
        int gm = m0 + row;
        if (gm >= cnt) gm = cnt - 1;
        size_t rowoff;
        if (FIRST) rowoff = (size_t)d_tok[e * TT + gm] * HH;
        else       rowoff = (size_t)(offs + gm) * II;
        aG[j]    = Aglob + rowoff + c * 8;
        aSoff[j] = row * (BKW * 4) + c * 16;
    }
    const __half* bG[4]; uint32_t bSoff[4];
#pragma unroll
    for (int j = 0; j < 4; j++) {
        int idx = tid + j * 256;
        int row = idx >> 2, c = idx & 3;
        bG[j]    = Wt + (size_t)e * ((size_t)II * HH) + (size_t)(n0 + row) * KDIM + c * 8;
        bSoff[j] = A_STAGE_B + row * (BKW * 4) + c * 16;
    }

    // prologue: stages 0,1
#pragma unroll
    for (int s = 0; s < NSTAGE - 1; s++) {
        uint32_t so = sbase + s * STAGE_B;
#pragma unroll
        for (int j = 0; j < 2; j++) CP_ASYNC16(so + aSoff[j], aG[j] + s * BK);
#pragma unroll
        for (int j = 0; j < 4; j++) CP_ASYNC16(so + bSoff[j], bG[j] + s * BK);
        CP_COMMIT();
    }

    const int wid = tid >> 5, lane = tid & 31;
    const int wm = (wid & 1) * 64;
    const int wn = (wid >> 1) * 64;
    const int g = lane >> 2, tg = lane & 3;

    float acc[4][8][4];
#pragma unroll
    for (int a = 0; a < 4; a++)
#pragma unroll
        for (int b = 0; b < 8; b++)
#pragma unroll
            for (int c = 0; c < 4; c++) acc[a][b][c] = 0.0f;

    int stage = 0;
    for (int i = 0; i < NC; i++) {
        CP_WAIT1();
        __syncthreads();

        const int nx = i + NSTAGE - 1;
        if (nx < NC) {
            int s = nx % NSTAGE;
            uint32_t so = sbase + s * STAGE_B;
#pragma unroll
            for (int j = 0; j < 2; j++) CP_ASYNC16(so + aSoff[j], aG[j] + nx * BK);
#pragma unroll
            for (int j = 0; j < 4; j++) CP_ASYNC16(so + bSoff[j], bG[j] + nx * BK);
        }
        CP_COMMIT();

        const uint32_t* As = (const uint32_t*)(dynsmem + stage * STAGE_B);
        const uint32_t* Bs = (const uint32_t*)(dynsmem + stage * STAGE_B + A_STAGE_B);

        // two k16 steps per BK=32 tile; word base w = kk*8
#pragma unroll
        for (int kk = 0; kk < 2; kk++) {
            const int w = kk * 8;
            uint32_t af[4][4], bf[8][2];
#pragma unroll
            for (int mf = 0; mf < 4; mf++) {
                int m = wm + mf * 16 + g;
                af[mf][0] = As[m * BKW + w + tg];          // row g,   k=2tg..
                af[mf][1] = As[(m + 8) * BKW + w + tg];    // row g+8
                af[mf][2] = As[m * BKW + w + tg + 4];      // row g,   k=2tg+8..
                af[mf][3] = As[(m + 8) * BKW + w + tg + 4];
            }
#pragma unroll
            for (int nf = 0; nf < 8; nf++) {
                int n = wn + nf * 8 + g;
                bf[nf][0] = Bs[n * BKW + w + tg];
                bf[nf][1] = Bs[n * BKW + w + tg + 4];
            }
#pragma unroll
            for (int mf = 0; mf < 4; mf++)
#pragma unroll
                for (int nf = 0; nf < 8; nf++)
                    MMA_F16(acc[mf][nf], af[mf], bf[nf]);
        }
        stage = (stage + 1 == NSTAGE) ? 0 : stage + 1;
    }

    // epilogue (acc layout: d0,d1 = row g cols 2tg,2tg+1; d2,d3 = row g+8)
#pragma unroll
    for (int mf = 0; mf < 4; mf++) {
#pragma unroll
        for (int half = 0; half < 2; half++) {
            int m = m0 + wm + mf * 16 + g + half * 8;
            if (m >= cnt) continue;
            if (FIRST) {
                __half* dst = d_hmid + (size_t)(offs + m) * II + n0;
#pragma unroll
                for (int nf = 0; nf < 8; nf++) {
                    int col = wn + nf * 8 + tg * 2;
                    float bb0 = bias[(size_t)e * NDIM + n0 + col];
                    float bb1 = bias[(size_t)e * NDIM + n0 + col + 1];
                    float s0 = silu_f(acc[mf][nf][half * 2 + 0] + bb0);
                    float s1 = silu_f(acc[mf][nf][half * 2 + 1] + bb1);
                    *(__half2*)(dst + col) = __floats2half2_rn(s0, s1);
                }
            } else {
                int tok = d_tok[e * TT + m];
                float w = d_wt[e * TT + m];
                float* dst = out + (size_t)tok * HH + n0;
#pragma unroll
                for (int nf = 0; nf < 8; nf++) {
                    int col = wn + nf * 8 + tg * 2;
                    float bb0 = bias[(size_t)e * NDIM + n0 + col];
                    float bb1 = bias[(size_t)e * NDIM + n0 + col + 1];
                    atomicAdd(dst + col,     w * (acc[mf][nf][half * 2 + 0] + bb0));
                    atomicAdd(dst + col + 1, w * (acc[mf][nf][half * 2 + 1] + bb1));
                }
            }
        }
    }
}

// ---------------- launch ----------------
extern "C" void kernel_launch(void* const* d_in, const int* in_sizes, int n_in,
                              void* d_out, int out_size) {
    const float* x  = (const float*)d_in[0];   // [T,H]
    const float* Wg = (const float*)d_in[1];   // [E,H]
    const float* W1 = (const float*)d_in[2];   // [E,I,H]
    const float* b1 = (const float*)d_in[3];   // [E,I]
    const float* W2 = (const float*)d_in[4];   // [E,H,I]
    const float* b2 = (const float*)d_in[5];   // [E,H]
    float* out = (float*)d_out;

    float* logits = nullptr;
    if ((size_t)out_size >= (size_t)TT * HH + (size_t)TT * EE)
        logits = out + (size_t)TT * HH;

    cudaFuncSetAttribute(moe_gemm_kernel<true>,  cudaFuncAttributeMaxDynamicSharedMemorySize, SMEM_DYN);
    cudaFuncSetAttribute(moe_gemm_kernel<false>, cudaFuncAttributeMaxDynamicSharedMemorySize, SMEM_DYN);

    init_counts_kernel<<<1, 32>>>();
    router_kernel<<<TT / 8, 256>>>(x, Wg, logits);
    scan_kernel<<<1, 1>>>();
    cudaMemsetAsync(out, 0, (size_t)TT * HH * sizeof(float), 0);

    cvt_f16_kernel<<<2048, 256>>>((const float4*)x,  0, (size_t)TT * HH / 4);
    cvt_f16_kernel<<<2048, 256>>>((const float4*)W1, 1, (size_t)EE * II * HH / 4);
    cvt_f16_kernel<<<2048, 256>>>((const float4*)W2, 2, (size_t)EE * HH * II / 4);

    dim3 g1(II / BN, TT / BM, EE);   // (16, 128, 8)
    moe_gemm_kernel<true><<<g1, 256, SMEM_DYN>>>(b1, nullptr);

    dim3 g2(HH / BN, TT / BM, EE);   // (4, 128, 8)
    moe_gemm_kernel<false><<<g2, 256, SMEM_DYN>>>(b2, out);
}

// round 6
// speedup vs baseline: 2.0541x; 1.0264x over previous
#include <cuda_runtime.h>
#include <cuda_fp16.h>
#include <cstdint>

// Problem constants
#define TT 16384   // B*S tokens
#define HH 1024    // hidden
#define II 4096    // intermediate
#define EE 8       // experts

// ---------------- scratch (device globals; no runtime allocation) ----------
__device__ int    d_counts[EE];
__device__ int    d_offsets[EE];
__device__ int    d_tok[EE * TT];
__device__ float  d_wt[EE * TT];
__device__ __half d_hmid[(size_t)2 * TT * II];    // fp16 intermediate (268 MB)
__device__ __half d_xh[(size_t)TT * HH];          // fp16 x
__device__ __half d_w1h[(size_t)EE * II * HH];    // fp16 W1
__device__ __half d_w2h[(size_t)EE * HH * II];    // fp16 W2

// ---------------- helpers ----------------
__device__ __forceinline__ float silu_f(float v) { return v / (1.0f + __expf(-v)); }
__device__ __forceinline__ uint32_t smem_u32(const void* p) {
    uint32_t a;
    asm("{ .reg .u64 t; cvta.to.shared.u64 t, %1; cvt.u32.u64 %0, t; }" : "=r"(a) : "l"(p));
    return a;
}

#define MMA_F16(D, A, B_)                                                        \
    asm volatile(                                                                \
        "mma.sync.aligned.m16n8k16.row.col.f32.f16.f16.f32 "                     \
        "{%0,%1,%2,%3}, {%4,%5,%6,%7}, {%8,%9}, {%0,%1,%2,%3};\n"                \
        : "+f"((D)[0]), "+f"((D)[1]), "+f"((D)[2]), "+f"((D)[3])                 \
        : "r"((A)[0]), "r"((A)[1]), "r"((A)[2]), "r"((A)[3]),                    \
          "r"((B_)[0]), "r"((B_)[1]))

#define LDSM_X4(r0, r1, r2, r3, addr)                                            \
    asm volatile("ldmatrix.sync.aligned.m8n8.x4.shared.b16 {%0,%1,%2,%3}, [%4];" \
        : "=r"(r0), "=r"(r1), "=r"(r2), "=r"(r3) : "r"(addr))

#define CP_ASYNC16(saddr, gptr) \
    asm volatile("cp.async.cg.shared.global [%0], [%1], 16;" :: "r"(saddr), "l"(gptr) : "memory")
#define CP_COMMIT() asm volatile("cp.async.commit_group;" ::: "memory")
#define CP_WAIT1()  asm volatile("cp.async.wait_group 1;" ::: "memory")

// ---------------- kernel: fp32 -> fp16 conversion pass (+zero counters) ----
__global__ __launch_bounds__(256)
void cvt_f16_kernel(const float4* __restrict__ src, int which, size_t n4) {
    if (which == 0 && blockIdx.x == 0 && threadIdx.x < EE)
        d_counts[threadIdx.x] = 0;
    __half* dstb = (which == 0) ? d_xh : (which == 1) ? d_w1h : d_w2h;
    uint2* dst = (uint2*)dstb;
    size_t i  = (size_t)blockIdx.x * blockDim.x + threadIdx.x;
    size_t st = (size_t)gridDim.x * blockDim.x;
    for (; i < n4; i += st) {
        float4 v = src[i];
        __half2 h0 = __floats2half2_rn(v.x, v.y);
        __half2 h1 = __floats2half2_rn(v.z, v.w);
        uint2 o;
        o.x = *(uint32_t*)&h0;
        o.y = *(uint32_t*)&h1;
        dst[i] = o;
    }
}

// ---------------- kernel: router (fp32) ----------------
__global__ __launch_bounds__(256)
void router_kernel(const float* __restrict__ x,
                   const float* __restrict__ Wg,
                   float* __restrict__ logits_out) {
    __shared__ float sWg[EE][HH];
    for (int i = threadIdx.x; i < EE * HH; i += blockDim.x)
        sWg[i / HH][i % HH] = Wg[i];
    __syncthreads();

    const int warp = threadIdx.x >> 5;
    const int lane = threadIdx.x & 31;
    const int t = blockIdx.x * 8 + warp;
    if (t >= TT) return;

    const float* xr = x + (size_t)t * HH;
    float acc[EE];
#pragma unroll
    for (int e = 0; e < EE; e++) acc[e] = 0.0f;
    for (int k = lane; k < HH; k += 32) {
        float xv = xr[k];
#pragma unroll
        for (int e = 0; e < EE; e++) acc[e] += xv * sWg[e][k];
    }
#pragma unroll
    for (int off = 16; off > 0; off >>= 1)
#pragma unroll
        for (int e = 0; e < EE; e++)
            acc[e] += __shfl_xor_sync(0xFFFFFFFFu, acc[e], off);

    if (lane == 0) {
        if (logits_out)
#pragma unroll
            for (int e = 0; e < EE; e++) logits_out[(size_t)t * EE + e] = acc[e];
        int i0 = 0; float v0 = acc[0];
#pragma unroll
        for (int e = 1; e < EE; e++) if (acc[e] > v0) { v0 = acc[e]; i0 = e; }
        int i1 = -1; float v1 = -3.4e38f;
#pragma unroll
        for (int e = 0; e < EE; e++)
            if (e != i0 && acc[e] > v1) { v1 = acc[e]; i1 = e; }
        float r  = expf(v1 - v0);
        float w0 = 1.0f / (1.0f + r);
        float w1 = 1.0f - w0;
        int p0 = atomicAdd(&d_counts[i0], 1);
        d_tok[i0 * TT + p0] = t;  d_wt[i0 * TT + p0] = w0;
        int p1 = atomicAdd(&d_counts[i1], 1);
        d_tok[i1 * TT + p1] = t;  d_wt[i1 * TT + p1] = w1;
    }
}

// ---------------- kernel: prefix scan ----------------
__global__ void scan_kernel() {
    int off = 0;
#pragma unroll
    for (int e = 0; e < EE; e++) { d_offsets[e] = off; off += d_counts[e]; }
}

// ---------------- GEMM: fp16 m16n8k16, 128x256 CTA, BK=32, 3-stage ------
// 8 warps, 64x64 per warp, ldmatrix fragment loads.
constexpr int BM = 128, BN = 256, BK = 32;
constexpr int BKW = 20;                            // padded words/row (16 data + 4 pad)
constexpr int A_STAGE_B = BM * BKW * 4;            // 10240 B
constexpr int B_STAGE_B = BN * BKW * 4;            // 20480 B
constexpr int STAGE_B   = A_STAGE_B + B_STAGE_B;   // 30720 B
constexpr int NSTAGE    = 3;
constexpr int SMEM_DYN  = NSTAGE * STAGE_B;        // 92160 B

template <bool FIRST>
__global__ __launch_bounds__(256, 1)
void moe_gemm_kernel(const float* __restrict__ bias, float* __restrict__ out) {
    const int e   = blockIdx.z;
    const int cnt = d_counts[e];
    const int m0  = blockIdx.y * BM;
    if (m0 >= cnt) return;
    const int n0   = blockIdx.x * BN;
    const int KDIM = FIRST ? HH : II;
    const int NDIM = FIRST ? II : HH;
    const int offs = d_offsets[e];
    const int NC   = KDIM / BK;

    extern __shared__ char dynsmem[];
    const uint32_t sbase = smem_u32(dynsmem);

    const int tid = threadIdx.x;
    const __half* Aglob = FIRST ? d_xh : d_hmid;
    const __half* Wt    = FIRST ? d_w1h : d_w2h;

    // cp.async loaders: A 2 chunks/thread, B 4 chunks/thread (16B each)
    const __half* aG[2]; uint32_t aSoff[2];
#pragma unroll
    for (int j = 0; j < 2; j++) {
        int idx = tid + j * 256;
        int row = idx >> 2, c = idx & 3;
        int gm = m0 + row;
        if (gm >= cnt) gm = cnt - 1;
        size_t rowoff;
        if (FIRST) rowoff = (size_t)d_tok[e * TT + gm] * HH;
        else       rowoff = (size_t)(offs + gm) * II;
        aG[j]    = Aglob + rowoff + c * 8;
        aSoff[j] = row * (BKW * 4) + c * 16;
    }
    const __half* bG[4]; uint32_t bSoff[4];
#pragma unroll
    for (int j = 0; j < 4; j++) {
        int idx = tid + j * 256;
        int row = idx >> 2, c = idx & 3;
        bG[j]    = Wt + (size_t)e * ((size_t)II * HH) + (size_t)(n0 + row) * KDIM + c * 8;
        bSoff[j] = A_STAGE_B + row * (BKW * 4) + c * 16;
    }

    // prologue: stages 0,1
#pragma unroll
    for (int s = 0; s < NSTAGE - 1; s++) {
        uint32_t so = sbase + s * STAGE_B;
#pragma unroll
        for (int j = 0; j < 2; j++) CP_ASYNC16(so + aSoff[j], aG[j] + s * BK);
#pragma unroll
        for (int j = 0; j < 4; j++) CP_ASYNC16(so + bSoff[j], bG[j] + s * BK);
        CP_COMMIT();
    }

    const int wid = tid >> 5, lane = tid & 31;
    const int wm = (wid & 1) * 64;
    const int wn = (wid >> 1) * 64;
    const int g = lane >> 2, tg = lane & 3;

    // ldmatrix per-lane base addresses
    uint32_t aLd[4];
#pragma unroll
    for (int mf = 0; mf < 4; mf++) {
        int row = wm + mf * 16 + (lane & 7) + ((lane >> 3) & 1) * 8;
        int col = ((lane >> 4) & 1) * 16;
        aLd[mf] = sbase + row * (BKW * 4) + col;
    }
    uint32_t bLd[4];
#pragma unroll
    for (int nf2 = 0; nf2 < 4; nf2++) {
        int row = wn + nf2 * 16 + (lane & 7) + ((lane >> 4) & 1) * 8;
        int col = ((lane >> 3) & 1) * 16;
        bLd[nf2] = sbase + A_STAGE_B + row * (BKW * 4) + col;
    }

    float acc[4][8][4];
#pragma unroll
    for (int a = 0; a < 4; a++)
#pragma unroll
        for (int b = 0; b < 8; b++)
#pragma unroll
            for (int c = 0; c < 4; c++) acc[a][b][c] = 0.0f;

    int stage = 0;
    for (int i = 0; i < NC; i++) {
        CP_WAIT1();
        __syncthreads();

        const int nx = i + NSTAGE - 1;
        if (nx < NC) {
            int s = nx % NSTAGE;
            uint32_t so = sbase + s * STAGE_B;
#pragma unroll
            for (int j = 0; j < 2; j++) CP_ASYNC16(so + aSoff[j], aG[j] + nx * BK);
#pragma unroll
            for (int j = 0; j < 4; j++) CP_ASYNC16(so + bSoff[j], bG[j] + nx * BK);
        }
        CP_COMMIT();

        const uint32_t stoff = stage * STAGE_B;
#pragma unroll
        for (int kk = 0; kk < 2; kk++) {
            const uint32_t ko = stoff + kk * 32;
            uint32_t af[4][4], bf[8][2];
#pragma unroll
            for (int mf = 0; mf < 4; mf++)
                LDSM_X4(af[mf][0], af[mf][1], af[mf][2], af[mf][3], aLd[mf] + ko);
#pragma unroll
            for (int nf2 = 0; nf2 < 4; nf2++)
                LDSM_X4(bf[nf2 * 2][0], bf[nf2 * 2][1],
                        bf[nf2 * 2 + 1][0], bf[nf2 * 2 + 1][1], bLd[nf2] + ko);
#pragma unroll
            for (int mf = 0; mf < 4; mf++)
#pragma unroll
                for (int nf = 0; nf < 8; nf++)
                    MMA_F16(acc[mf][nf], af[mf], bf[nf]);
        }
        stage = (stage + 1 == NSTAGE) ? 0 : stage + 1;
    }

    // epilogue (acc: d0,d1 = row g cols 2tg,2tg+1; d2,d3 = row g+8)
#pragma unroll
    for (int mf = 0; mf < 4; mf++) {
#pragma unroll
        for (int half = 0; half < 2; half++) {
            int m = m0 + wm + mf * 16 + g + half * 8;
            if (m >= cnt) continue;
            if (FIRST) {
                __half* dst = d_hmid + (size_t)(offs + m) * II + n0;
#pragma unroll
                for (int nf = 0; nf < 8; nf++) {
                    int col = wn + nf * 8 + tg * 2;
                    float bb0 = bias[(size_t)e * NDIM + n0 + col];
                    float bb1 = bias[(size_t)e * NDIM + n0 + col + 1];
                    float s0 = silu_f(acc[mf][nf][half * 2 + 0] + bb0);
                    float s1 = silu_f(acc[mf][nf][half * 2 + 1] + bb1);
                    *(__half2*)(dst + col) = __floats2half2_rn(s0, s1);
                }
            } else {
                int tok = d_tok[e * TT + m];
                float w = d_wt[e * TT + m];
                float* dst = out + (size_t)tok * HH + n0;
#pragma unroll
                for (int nf = 0; nf < 8; nf++) {
                    int col = wn + nf * 8 + tg * 2;
                    float bb0 = bias[(size_t)e * NDIM + n0 + col];
                    float bb1 = bias[(size_t)e * NDIM + n0 + col + 1];
                    atomicAdd(dst + col,     w * (acc[mf][nf][half * 2 + 0] + bb0));
                    atomicAdd(dst + col + 1, w * (acc[mf][nf][half * 2 + 1] + bb1));
                }
            }
        }
    }
}

// ---------------- launch ----------------
extern "C" void kernel_launch(void* const* d_in, const int* in_sizes, int n_in,
                              void* d_out, int out_size) {
    const float* x  = (const float*)d_in[0];   // [T,H]
    const float* Wg = (const float*)d_in[1];   // [E,H]
    const float* W1 = (const float*)d_in[2];   // [E,I,H]
    const float* b1 = (const float*)d_in[3];   // [E,I]
    const float* W2 = (const float*)d_in[4];   // [E,H,I]
    const float* b2 = (const float*)d_in[5];   // [E,H]
    float* out = (float*)d_out;

    float* logits = nullptr;
    if ((size_t)out_size >= (size_t)TT * HH + (size_t)TT * EE)
        logits = out + (size_t)TT * HH;

    cudaFuncSetAttribute(moe_gemm_kernel<true>,  cudaFuncAttributeMaxDynamicSharedMemorySize, SMEM_DYN);
    cudaFuncSetAttribute(moe_gemm_kernel<false>, cudaFuncAttributeMaxDynamicSharedMemorySize, SMEM_DYN);

    // launch order: 5 kernels precede gemm1 so ncu (-s 5 -c 1) profiles it
    cvt_f16_kernel<<<2048, 256>>>((const float4*)x,  0, (size_t)TT * HH / 4);   // also zeroes counts
    cvt_f16_kernel<<<2048, 256>>>((const float4*)W1, 1, (size_t)EE * II * HH / 4);
    cvt_f16_kernel<<<2048, 256>>>((const float4*)W2, 2, (size_t)EE * HH * II / 4);
    router_kernel<<<TT / 8, 256>>>(x, Wg, logits);
    scan_kernel<<<1, 1>>>();
    cudaMemsetAsync(out, 0, (size_t)TT * HH * sizeof(float), 0);

    dim3 g1(II / BN, TT / BM, EE);   // (16, 128, 8)
    moe_gemm_kernel<true><<<g1, 256, SMEM_DYN>>>(b1, nullptr);

    dim3 g2(HH / BN, TT / BM, EE);   // (4, 128, 8)
    moe_gemm_kernel<false><<<g2, 256, SMEM_DYN>>>(b2, out);
}

// round 7
// speedup vs baseline: 2.4235x; 1.1798x over previous
#include <cuda_runtime.h>
#include <cuda_fp16.h>
#include <cstdint>

// Problem constants
#define TT 16384   // B*S tokens
#define HH 1024    // hidden
#define II 4096    // intermediate
#define EE 8       // experts

// ---------------- scratch (device globals; no runtime allocation) ----------
__device__ int    d_counts[EE];
__device__ int    d_offsets[EE];
__device__ int    d_tok[EE * TT];
__device__ float  d_wt[EE * TT];
__device__ __half d_hmid[(size_t)2 * TT * II];    // fp16 intermediate (268 MB)
__device__ __half d_xh[(size_t)TT * HH];          // fp16 x
__device__ __half d_w1h[(size_t)EE * II * HH];    // fp16 W1
__device__ __half d_w2h[(size_t)EE * HH * II];    // fp16 W2

// ---------------- helpers ----------------
__device__ __forceinline__ float silu_f(float v) { return v / (1.0f + __expf(-v)); }
__device__ __forceinline__ uint32_t smem_u32(const void* p) {
    uint32_t a;
    asm("{ .reg .u64 t; cvta.to.shared.u64 t, %1; cvt.u32.u64 %0, t; }" : "=r"(a) : "l"(p));
    return a;
}

#define MMA_F16(D, A, B_)                                                        \
    asm volatile(                                                                \
        "mma.sync.aligned.m16n8k16.row.col.f32.f16.f16.f32 "                     \
        "{%0,%1,%2,%3}, {%4,%5,%6,%7}, {%8,%9}, {%0,%1,%2,%3};\n"                \
        : "+f"((D)[0]), "+f"((D)[1]), "+f"((D)[2]), "+f"((D)[3])                 \
        : "r"((A)[0]), "r"((A)[1]), "r"((A)[2]), "r"((A)[3]),                    \
          "r"((B_)[0]), "r"((B_)[1]))

#define LDSM_X4(r0, r1, r2, r3, addr)                                            \
    asm volatile("ldmatrix.sync.aligned.m8n8.x4.shared.b16 {%0,%1,%2,%3}, [%4];" \
        : "=r"(r0), "=r"(r1), "=r"(r2), "=r"(r3) : "r"(addr))

#define CP_ASYNC16(saddr, gptr) \
    asm volatile("cp.async.cg.shared.global [%0], [%1], 16;" :: "r"(saddr), "l"(gptr) : "memory")
#define CP_COMMIT() asm volatile("cp.async.commit_group;" ::: "memory")
#define CP_WAIT1()  asm volatile("cp.async.wait_group 1;" ::: "memory")

// ---------------- kernel: fp32 -> fp16 conversion pass (+zero counters) ----
__global__ __launch_bounds__(256)
void cvt_f16_kernel(const float4* __restrict__ src, int which, size_t n4) {
    if (which == 0 && blockIdx.x == 0 && threadIdx.x < EE)
        d_counts[threadIdx.x] = 0;
    __half* dstb = (which == 0) ? d_xh : (which == 1) ? d_w1h : d_w2h;
    uint2* dst = (uint2*)dstb;
    size_t i  = (size_t)blockIdx.x * blockDim.x + threadIdx.x;
    size_t st = (size_t)gridDim.x * blockDim.x;
    for (; i < n4; i += st) {
        float4 v = src[i];
        __half2 h0 = __floats2half2_rn(v.x, v.y);
        __half2 h1 = __floats2half2_rn(v.z, v.w);
        uint2 o;
        o.x = *(uint32_t*)&h0;
        o.y = *(uint32_t*)&h1;
        dst[i] = o;
    }
}

// ---------------- kernel: router (fp32) ----------------
__global__ __launch_bounds__(256)
void router_kernel(const float* __restrict__ x,
                   const float* __restrict__ Wg,
                   float* __restrict__ logits_out) {
    __shared__ float sWg[EE][HH];
    for (int i = threadIdx.x; i < EE * HH; i += blockDim.x)
        sWg[i / HH][i % HH] = Wg[i];
    __syncthreads();

    const int warp = threadIdx.x >> 5;
    const int lane = threadIdx.x & 31;
    const int t = blockIdx.x * 8 + warp;
    if (t >= TT) return;

    const float* xr = x + (size_t)t * HH;
    float acc[EE];
#pragma unroll
    for (int e = 0; e < EE; e++) acc[e] = 0.0f;
    for (int k = lane; k < HH; k += 32) {
        float xv = xr[k];
#pragma unroll
        for (int e = 0; e < EE; e++) acc[e] += xv * sWg[e][k];
    }
#pragma unroll
    for (int off = 16; off > 0; off >>= 1)
#pragma unroll
        for (int e = 0; e < EE; e++)
            acc[e] += __shfl_xor_sync(0xFFFFFFFFu, acc[e], off);

    if (lane == 0) {
        if (logits_out)
#pragma unroll
            for (int e = 0; e < EE; e++) logits_out[(size_t)t * EE + e] = acc[e];
        int i0 = 0; float v0 = acc[0];
#pragma unroll
        for (int e = 1; e < EE; e++) if (acc[e] > v0) { v0 = acc[e]; i0 = e; }
        int i1 = -1; float v1 = -3.4e38f;
#pragma unroll
        for (int e = 0; e < EE; e++)
            if (e != i0 && acc[e] > v1) { v1 = acc[e]; i1 = e; }
        float r  = expf(v1 - v0);
        float w0 = 1.0f / (1.0f + r);
        float w1 = 1.0f - w0;
        int p0 = atomicAdd(&d_counts[i0], 1);
        d_tok[i0 * TT + p0] = t;  d_wt[i0 * TT + p0] = w0;
        int p1 = atomicAdd(&d_counts[i1], 1);
        d_tok[i1 * TT + p1] = t;  d_wt[i1 * TT + p1] = w1;
    }
}

// ---------------- kernel: prefix scan ----------------
__global__ void scan_kernel() {
    int off = 0;
#pragma unroll
    for (int e = 0; e < EE; e++) { d_offsets[e] = off; off += d_counts[e]; }
}

// ---------------- GEMM: fp16 m16n8k16, 128x128 CTA, 2 CTAs/SM -----------
// 8 warps (2m x 4n), 64x32 per warp, ldmatrix fragment loads, 3-stage.
constexpr int BM = 128, BN = 128, BK = 32;
constexpr int BKW = 20;                            // padded words/row
constexpr int A_STAGE_B = BM * BKW * 4;            // 10240 B
constexpr int B_STAGE_B = BN * BKW * 4;            // 10240 B
constexpr int STAGE_B   = A_STAGE_B + B_STAGE_B;   // 20480 B
constexpr int NSTAGE    = 3;
constexpr int SMEM_DYN  = NSTAGE * STAGE_B;        // 61440 B (2 CTAs -> 120 KB/SM)

template <bool FIRST>
__global__ __launch_bounds__(256, 2)
void moe_gemm_kernel(const float* __restrict__ bias, float* __restrict__ out) {
    const int e   = blockIdx.z;
    const int cnt = d_counts[e];
    const int m0  = blockIdx.y * BM;
    if (m0 >= cnt) return;
    const int n0   = blockIdx.x * BN;
    const int KDIM = FIRST ? HH : II;
    const int NDIM = FIRST ? II : HH;
    const int offs = d_offsets[e];
    const int NC   = KDIM / BK;

    extern __shared__ char dynsmem[];
    const uint32_t sbase = smem_u32(dynsmem);

    const int tid = threadIdx.x;
    const __half* Aglob = FIRST ? d_xh : d_hmid;
    const __half* Wt    = FIRST ? d_w1h : d_w2h;

    // cp.async loaders: A 2 chunks/thread, B 2 chunks/thread (16B each)
    const __half* aG[2]; uint32_t aSoff[2];
#pragma unroll
    for (int j = 0; j < 2; j++) {
        int idx = tid + j * 256;
        int row = idx >> 2, c = idx & 3;
        int gm = m0 + row;
        if (gm >= cnt) gm = cnt - 1;
        size_t rowoff;
        if (FIRST) rowoff = (size_t)d_tok[e * TT + gm] * HH;
        else       rowoff = (size_t)(offs + gm) * II;
        aG[j]    = Aglob + rowoff + c * 8;
        aSoff[j] = row * (BKW * 4) + c * 16;
    }
    const __half* bG[2]; uint32_t bSoff[2];
#pragma unroll
    for (int j = 0; j < 2; j++) {
        int idx = tid + j * 256;
        int row = idx >> 2, c = idx & 3;
        bG[j]    = Wt + (size_t)e * ((size_t)II * HH) + (size_t)(n0 + row) * KDIM + c * 8;
        bSoff[j] = A_STAGE_B + row * (BKW * 4) + c * 16;
    }

    // prologue: stages 0,1
#pragma unroll
    for (int s = 0; s < NSTAGE - 1; s++) {
        uint32_t so = sbase + s * STAGE_B;
#pragma unroll
        for (int j = 0; j < 2; j++) CP_ASYNC16(so + aSoff[j], aG[j] + s * BK);
#pragma unroll
        for (int j = 0; j < 2; j++) CP_ASYNC16(so + bSoff[j], bG[j] + s * BK);
        CP_COMMIT();
    }

    const int wid = tid >> 5, lane = tid & 31;
    const int wm = (wid & 1) * 64;        // 2 m-warps
    const int wn = (wid >> 1) * 32;       // 4 n-warps
    const int g = lane >> 2, tg = lane & 3;

    // ldmatrix per-lane base addresses: A 4 frags (m16k16), B 2 frags (n16k16)
    uint32_t aLd[4];
#pragma unroll
    for (int mf = 0; mf < 4; mf++) {
        int row = wm + mf * 16 + (lane & 7) + ((lane >> 3) & 1) * 8;
        int col = ((lane >> 4) & 1) * 16;
        aLd[mf] = sbase + row * (BKW * 4) + col;
    }
    uint32_t bLd[2];
#pragma unroll
    for (int nf2 = 0; nf2 < 2; nf2++) {
        int row = wn + nf2 * 16 + (lane & 7) + ((lane >> 4) & 1) * 8;
        int col = ((lane >> 3) & 1) * 16;
        bLd[nf2] = sbase + A_STAGE_B + row * (BKW * 4) + col;
    }

    float acc[4][4][4];
#pragma unroll
    for (int a = 0; a < 4; a++)
#pragma unroll
        for (int b = 0; b < 4; b++)
#pragma unroll
            for (int c = 0; c < 4; c++) acc[a][b][c] = 0.0f;

    int stage = 0;
    for (int i = 0; i < NC; i++) {
        CP_WAIT1();
        __syncthreads();

        const int nx = i + NSTAGE - 1;
        if (nx < NC) {
            int s = nx % NSTAGE;
            uint32_t so = sbase + s * STAGE_B;
#pragma unroll
            for (int j = 0; j < 2; j++) CP_ASYNC16(so + aSoff[j], aG[j] + nx * BK);
#pragma unroll
            for (int j = 0; j < 2; j++) CP_ASYNC16(so + bSoff[j], bG[j] + nx * BK);
        }
        CP_COMMIT();

        const uint32_t stoff = stage * STAGE_B;
#pragma unroll
        for (int kk = 0; kk < 2; kk++) {
            const uint32_t ko = stoff + kk * 32;
            uint32_t af[4][4], bf[4][2];
#pragma unroll
            for (int mf = 0; mf < 4; mf++)
                LDSM_X4(af[mf][0], af[mf][1], af[mf][2], af[mf][3], aLd[mf] + ko);
#pragma unroll
            for (int nf2 = 0; nf2 < 2; nf2++)
                LDSM_X4(bf[nf2 * 2][0], bf[nf2 * 2][1],
                        bf[nf2 * 2 + 1][0], bf[nf2 * 2 + 1][1], bLd[nf2] + ko);
#pragma unroll
            for (int mf = 0; mf < 4; mf++)
#pragma unroll
                for (int nf = 0; nf < 4; nf++)
                    MMA_F16(acc[mf][nf], af[mf], bf[nf]);
        }
        stage = (stage + 1 == NSTAGE) ? 0 : stage + 1;
    }

    // epilogue (acc: d0,d1 = row g cols 2tg,2tg+1; d2,d3 = row g+8)
#pragma unroll
    for (int mf = 0; mf < 4; mf++) {
#pragma unroll
        for (int half = 0; half < 2; half++) {
            int m = m0 + wm + mf * 16 + g + half * 8;
            if (m >= cnt) continue;
            if (FIRST) {
                __half* dst = d_hmid + (size_t)(offs + m) * II + n0;
#pragma unroll
                for (int nf = 0; nf < 4; nf++) {
                    int col = wn + nf * 8 + tg * 2;
                    float bb0 = bias[(size_t)e * NDIM + n0 + col];
                    float bb1 = bias[(size_t)e * NDIM + n0 + col + 1];
                    float s0 = silu_f(acc[mf][nf][half * 2 + 0] + bb0);
                    float s1 = silu_f(acc[mf][nf][half * 2 + 1] + bb1);
                    *(__half2*)(dst + col) = __floats2half2_rn(s0, s1);
                }
            } else {
                int tok = d_tok[e * TT + m];
                float w = d_wt[e * TT + m];
                float* dst = out + (size_t)tok * HH + n0;
#pragma unroll
                for (int nf = 0; nf < 4; nf++) {
                    int col = wn + nf * 8 + tg * 2;
                    float bb0 = bias[(size_t)e * NDIM + n0 + col];
                    float bb1 = bias[(size_t)e * NDIM + n0 + col + 1];
                    atomicAdd(dst + col,     w * (acc[mf][nf][half * 2 + 0] + bb0));
                    atomicAdd(dst + col + 1, w * (acc[mf][nf][half * 2 + 1] + bb1));
                }
            }
        }
    }
}

// ---------------- launch ----------------
extern "C" void kernel_launch(void* const* d_in, const int* in_sizes, int n_in,
                              void* d_out, int out_size) {
    const float* x  = (const float*)d_in[0];   // [T,H]
    const float* Wg = (const float*)d_in[1];   // [E,H]
    const float* W1 = (const float*)d_in[2];   // [E,I,H]
    const float* b1 = (const float*)d_in[3];   // [E,I]
    const float* W2 = (const float*)d_in[4];   // [E,H,I]
    const float* b2 = (const float*)d_in[5];   // [E,H]
    float* out = (float*)d_out;

    float* logits = nullptr;
    if ((size_t)out_size >= (size_t)TT * HH + (size_t)TT * EE)
        logits = out + (size_t)TT * HH;

    cudaFuncSetAttribute(moe_gemm_kernel<true>,  cudaFuncAttributeMaxDynamicSharedMemorySize, SMEM_DYN);
    cudaFuncSetAttribute(moe_gemm_kernel<false>, cudaFuncAttributeMaxDynamicSharedMemorySize, SMEM_DYN);

    // gemm1 is the 6th kernel launch -> ncu -s 5 -c 1 profiles it
    cvt_f16_kernel<<<4096, 256>>>((const float4*)x,  0, (size_t)TT * HH / 4);   // also zeroes counts
    cvt_f16_kernel<<<4096, 256>>>((const float4*)W1, 1, (size_t)EE * II * HH / 4);
    cvt_f16_kernel<<<4096, 256>>>((const float4*)W2, 2, (size_t)EE * HH * II / 4);
    router_kernel<<<TT / 8, 256>>>(x, Wg, logits);
    scan_kernel<<<1, 1>>>();

    dim3 g1(II / BN, TT / BM, EE);   // (32, 128, 8)
    moe_gemm_kernel<true><<<g1, 256, SMEM_DYN>>>(b1, nullptr);

    cudaMemsetAsync(out, 0, (size_t)TT * HH * sizeof(float), 0);

    dim3 g2(HH / BN, TT / BM, EE);   // (8, 128, 8)
    moe_gemm_kernel<false><<<g2, 256, SMEM_DYN>>>(b2, out);
}

// round 8
// speedup vs baseline: 2.4795x; 1.0231x over previous
#include <cuda_runtime.h>
#include <cuda_fp16.h>
#include <cstdint>

// Problem constants
#define TT 16384   // B*S tokens
#define HH 1024    // hidden
#define II 4096    // intermediate
#define EE 8       // experts

// ---------------- scratch (device globals; no runtime allocation) ----------
__device__ int    d_counts[EE];
__device__ int    d_offsets[EE];
__device__ int    d_tok[EE * TT];
__device__ float  d_wt[EE * TT];
__device__ __half d_hmid[(size_t)2 * TT * II];    // fp16 intermediate (268 MB)
__device__ __half d_xh[(size_t)TT * HH];          // fp16 x
__device__ __half d_w1h[(size_t)EE * II * HH];    // fp16 W1
__device__ __half d_w2h[(size_t)EE * HH * II];    // fp16 W2

// ---------------- helpers ----------------
__device__ __forceinline__ float silu_f(float v) { return v / (1.0f + __expf(-v)); }
__device__ __forceinline__ uint32_t smem_u32(const void* p) {
    uint32_t a;
    asm("{ .reg .u64 t; cvta.to.shared.u64 t, %1; cvt.u32.u64 %0, t; }" : "=r"(a) : "l"(p));
    return a;
}

#define MMA_F16(D, A, B_)                                                        \
    asm volatile(                                                                \
        "mma.sync.aligned.m16n8k16.row.col.f32.f16.f16.f32 "                     \
        "{%0,%1,%2,%3}, {%4,%5,%6,%7}, {%8,%9}, {%0,%1,%2,%3};\n"                \
        : "+f"((D)[0]), "+f"((D)[1]), "+f"((D)[2]), "+f"((D)[3])                 \
        : "r"((A)[0]), "r"((A)[1]), "r"((A)[2]), "r"((A)[3]),                    \
          "r"((B_)[0]), "r"((B_)[1]))

#define LDSM_X4(r0, r1, r2, r3, addr)                                            \
    asm volatile("ldmatrix.sync.aligned.m8n8.x4.shared.b16 {%0,%1,%2,%3}, [%4];" \
        : "=r"(r0), "=r"(r1), "=r"(r2), "=r"(r3) : "r"(addr))

#define CP_ASYNC16(saddr, gptr) \
    asm volatile("cp.async.cg.shared.global [%0], [%1], 16;" :: "r"(saddr), "l"(gptr) : "memory")
#define CP_COMMIT() asm volatile("cp.async.commit_group;" ::: "memory")
#define CP_WAIT2()  asm volatile("cp.async.wait_group 2;" ::: "memory")

// ---------------- kernel: fp32 -> fp16 conversion pass (+zero counters) ----
__global__ __launch_bounds__(256)
void cvt_f16_kernel(const float4* __restrict__ src, int which, size_t n4) {
    if (which == 0 && blockIdx.x == 0 && threadIdx.x < EE)
        d_counts[threadIdx.x] = 0;
    __half* dstb = (which == 0) ? d_xh : (which == 1) ? d_w1h : d_w2h;
    uint2* dst = (uint2*)dstb;
    size_t i  = (size_t)blockIdx.x * blockDim.x + threadIdx.x;
    size_t st = (size_t)gridDim.x * blockDim.x;
    for (; i < n4; i += st) {
        float4 v = src[i];
        __half2 h0 = __floats2half2_rn(v.x, v.y);
        __half2 h1 = __floats2half2_rn(v.z, v.w);
        uint2 o;
        o.x = *(uint32_t*)&h0;
        o.y = *(uint32_t*)&h1;
        dst[i] = o;
    }
}

// ---------------- kernel: router (fp32) ----------------
__global__ __launch_bounds__(256)
void router_kernel(const float* __restrict__ x,
                   const float* __restrict__ Wg,
                   float* __restrict__ logits_out) {
    __shared__ float sWg[EE][HH];
    for (int i = threadIdx.x; i < EE * HH; i += blockDim.x)
        sWg[i / HH][i % HH] = Wg[i];
    __syncthreads();

    const int warp = threadIdx.x >> 5;
    const int lane = threadIdx.x & 31;
    const int t = blockIdx.x * 8 + warp;
    if (t >= TT) return;

    const float* xr = x + (size_t)t * HH;
    float acc[EE];
#pragma unroll
    for (int e = 0; e < EE; e++) acc[e] = 0.0f;
    for (int k = lane; k < HH; k += 32) {
        float xv = xr[k];
#pragma unroll
        for (int e = 0; e < EE; e++) acc[e] += xv * sWg[e][k];
    }
#pragma unroll
    for (int off = 16; off > 0; off >>= 1)
#pragma unroll
        for (int e = 0; e < EE; e++)
            acc[e] += __shfl_xor_sync(0xFFFFFFFFu, acc[e], off);

    if (lane == 0) {
        if (logits_out)
#pragma unroll
            for (int e = 0; e < EE; e++) logits_out[(size_t)t * EE + e] = acc[e];
        int i0 = 0; float v0 = acc[0];
#pragma unroll
        for (int e = 1; e < EE; e++) if (acc[e] > v0) { v0 = acc[e]; i0 = e; }
        int i1 = -1; float v1 = -3.4e38f;
#pragma unroll
        for (int e = 0; e < EE; e++)
            if (e != i0 && acc[e] > v1) { v1 = acc[e]; i1 = e; }
        float r  = expf(v1 - v0);
        float w0 = 1.0f / (1.0f + r);
        float w1 = 1.0f - w0;
        int p0 = atomicAdd(&d_counts[i0], 1);
        d_tok[i0 * TT + p0] = t;  d_wt[i0 * TT + p0] = w0;
        int p1 = atomicAdd(&d_counts[i1], 1);
        d_tok[i1 * TT + p1] = t;  d_wt[i1 * TT + p1] = w1;
    }
}

// ---------------- kernel: prefix scan ----------------
__global__ void scan_kernel() {
    int off = 0;
#pragma unroll
    for (int e = 0; e < EE; e++) { d_offsets[e] = off; off += d_counts[e]; }
}

// ---------------- GEMM: fp16 m16n8k16, 128x128 CTA, 2 CTAs/SM -----------
// 8 warps (2m x 4n), 64x32 per warp, ldmatrix loads, 4-stage cp.async.
constexpr int BM = 128, BN = 128, BK = 32;
constexpr int BKW = 20;                            // padded words/row
constexpr int A_STAGE_B = BM * BKW * 4;            // 10240 B
constexpr int B_STAGE_B = BN * BKW * 4;            // 10240 B
constexpr int STAGE_B   = A_STAGE_B + B_STAGE_B;   // 20480 B
constexpr int NSTAGE    = 4;
constexpr int SMEM_DYN  = NSTAGE * STAGE_B;        // 81920 B (2 CTAs -> 160 KB/SM)

template <bool FIRST>
__global__ __launch_bounds__(256, 2)
void moe_gemm_kernel(const float* __restrict__ bias, float* __restrict__ out) {
    const int e   = blockIdx.z;
    const int cnt = d_counts[e];
    const int m0  = blockIdx.y * BM;
    if (m0 >= cnt) return;
    const int n0   = blockIdx.x * BN;
    const int KDIM = FIRST ? HH : II;
    const int NDIM = FIRST ? II : HH;
    const int offs = d_offsets[e];
    const int NC   = KDIM / BK;

    extern __shared__ char dynsmem[];
    const uint32_t sbase = smem_u32(dynsmem);

    const int tid = threadIdx.x;
    const __half* Aglob = FIRST ? d_xh : d_hmid;
    const __half* Wt    = FIRST ? d_w1h : d_w2h;

    // cp.async loaders: A 2 chunks/thread, B 2 chunks/thread (16B each)
    const __half* aG[2]; uint32_t aSoff[2];
#pragma unroll
    for (int j = 0; j < 2; j++) {
        int idx = tid + j * 256;
        int row = idx >> 2, c = idx & 3;
        int gm = m0 + row;
        if (gm >= cnt) gm = cnt - 1;
        size_t rowoff;
        if (FIRST) rowoff = (size_t)d_tok[e * TT + gm] * HH;
        else       rowoff = (size_t)(offs + gm) * II;
        aG[j]    = Aglob + rowoff + c * 8;
        aSoff[j] = row * (BKW * 4) + c * 16;
    }
    const __half* bG[2]; uint32_t bSoff[2];
#pragma unroll
    for (int j = 0; j < 2; j++) {
        int idx = tid + j * 256;
        int row = idx >> 2, c = idx & 3;
        bG[j]    = Wt + (size_t)e * ((size_t)II * HH) + (size_t)(n0 + row) * KDIM + c * 8;
        bSoff[j] = A_STAGE_B + row * (BKW * 4) + c * 16;
    }

    // prologue: stages 0..2
#pragma unroll
    for (int s = 0; s < NSTAGE - 1; s++) {
        uint32_t so = sbase + s * STAGE_B;
#pragma unroll
        for (int j = 0; j < 2; j++) CP_ASYNC16(so + aSoff[j], aG[j] + s * BK);
#pragma unroll
        for (int j = 0; j < 2; j++) CP_ASYNC16(so + bSoff[j], bG[j] + s * BK);
        CP_COMMIT();
    }

    const int wid = tid >> 5, lane = tid & 31;
    const int wm = (wid & 1) * 64;        // 2 m-warps
    const int wn = (wid >> 1) * 32;       // 4 n-warps
    const int g = lane >> 2, tg = lane & 3;

    // ldmatrix per-lane base addresses: A 4 frags (m16k16), B 2 frags (n16k16)
    uint32_t aLd[4];
#pragma unroll
    for (int mf = 0; mf < 4; mf++) {
        int row = wm + mf * 16 + (lane & 7) + ((lane >> 3) & 1) * 8;
        int col = ((lane >> 4) & 1) * 16;
        aLd[mf] = sbase + row * (BKW * 4) + col;
    }
    uint32_t bLd[2];
#pragma unroll
    for (int nf2 = 0; nf2 < 2; nf2++) {
        int row = wn + nf2 * 16 + (lane & 7) + ((lane >> 4) & 1) * 8;
        int col = ((lane >> 3) & 1) * 16;
        bLd[nf2] = sbase + A_STAGE_B + row * (BKW * 4) + col;
    }

    float acc[4][4][4];
#pragma unroll
    for (int a = 0; a < 4; a++)
#pragma unroll
        for (int b = 0; b < 4; b++)
#pragma unroll
            for (int c = 0; c < 4; c++) acc[a][b][c] = 0.0f;

    int stage = 0;
    for (int i = 0; i < NC; i++) {
        CP_WAIT2();              // current stage resident; <=2 groups in flight
        __syncthreads();

        const int nx = i + NSTAGE - 1;
        if (nx < NC) {
            int s = nx & (NSTAGE - 1);
            uint32_t so = sbase + s * STAGE_B;
#pragma unroll
            for (int j = 0; j < 2; j++) CP_ASYNC16(so + aSoff[j], aG[j] + nx * BK);
#pragma unroll
            for (int j = 0; j < 2; j++) CP_ASYNC16(so + bSoff[j], bG[j] + nx * BK);
        }
        CP_COMMIT();

        const uint32_t stoff = stage * STAGE_B;
#pragma unroll
        for (int kk = 0; kk < 2; kk++) {
            const uint32_t ko = stoff + kk * 32;
            uint32_t af[4][4], bf[4][2];
#pragma unroll
            for (int mf = 0; mf < 4; mf++)
                LDSM_X4(af[mf][0], af[mf][1], af[mf][2], af[mf][3], aLd[mf] + ko);
#pragma unroll
            for (int nf2 = 0; nf2 < 2; nf2++)
                LDSM_X4(bf[nf2 * 2][0], bf[nf2 * 2][1],
                        bf[nf2 * 2 + 1][0], bf[nf2 * 2 + 1][1], bLd[nf2] + ko);
#pragma unroll
            for (int mf = 0; mf < 4; mf++)
#pragma unroll
                for (int nf = 0; nf < 4; nf++)
                    MMA_F16(acc[mf][nf], af[mf], bf[nf]);
        }
        stage = (stage + 1) & (NSTAGE - 1);
    }

    // epilogue (acc: d0,d1 = row g cols 2tg,2tg+1; d2,d3 = row g+8)
#pragma unroll
    for (int mf = 0; mf < 4; mf++) {
#pragma unroll
        for (int half = 0; half < 2; half++) {
            int m = m0 + wm + mf * 16 + g + half * 8;
            if (m >= cnt) continue;
            if (FIRST) {
                __half* dst = d_hmid + (size_t)(offs + m) * II + n0;
#pragma unroll
                for (int nf = 0; nf < 4; nf++) {
                    int col = wn + nf * 8 + tg * 2;
                    float bb0 = bias[(size_t)e * NDIM + n0 + col];
                    float bb1 = bias[(size_t)e * NDIM + n0 + col + 1];
                    float s0 = silu_f(acc[mf][nf][half * 2 + 0] + bb0);
                    float s1 = silu_f(acc[mf][nf][half * 2 + 1] + bb1);
                    *(__half2*)(dst + col) = __floats2half2_rn(s0, s1);
                }
            } else {
                int tok = d_tok[e * TT + m];
                float w = d_wt[e * TT + m];
                float* dst = out + (size_t)tok * HH + n0;
#pragma unroll
                for (int nf = 0; nf < 4; nf++) {
                    int col = wn + nf * 8 + tg * 2;
                    float bb0 = bias[(size_t)e * NDIM + n0 + col];
                    float bb1 = bias[(size_t)e * NDIM + n0 + col + 1];
                    atomicAdd(dst + col,     w * (acc[mf][nf][half * 2 + 0] + bb0));
                    atomicAdd(dst + col + 1, w * (acc[mf][nf][half * 2 + 1] + bb1));
                }
            }
        }
    }
}

// ---------------- launch ----------------
extern "C" void kernel_launch(void* const* d_in, const int* in_sizes, int n_in,
                              void* d_out, int out_size) {
    const float* x  = (const float*)d_in[0];   // [T,H]
    const float* Wg = (const float*)d_in[1];   // [E,H]
    const float* W1 = (const float*)d_in[2];   // [E,I,H]
    const float* b1 = (const float*)d_in[3];   // [E,I]
    const float* W2 = (const float*)d_in[4];   // [E,H,I]
    const float* b2 = (const float*)d_in[5];   // [E,H]
    float* out = (float*)d_out;

    float* logits = nullptr;
    if ((size_t)out_size >= (size_t)TT * HH + (size_t)TT * EE)
        logits = out + (size_t)TT * HH;

    cudaFuncSetAttribute(moe_gemm_kernel<true>,  cudaFuncAttributeMaxDynamicSharedMemorySize, SMEM_DYN);
    cudaFuncSetAttribute(moe_gemm_kernel<false>, cudaFuncAttributeMaxDynamicSharedMemorySize, SMEM_DYN);

    cvt_f16_kernel<<<4096, 256>>>((const float4*)x,  0, (size_t)TT * HH / 4);   // also zeroes counts
    cvt_f16_kernel<<<4096, 256>>>((const float4*)W1, 1, (size_t)EE * II * HH / 4);
    cvt_f16_kernel<<<4096, 256>>>((const float4*)W2, 2, (size_t)EE * HH * II / 4);
    router_kernel<<<TT / 8, 256>>>(x, Wg, logits);
    scan_kernel<<<1, 1>>>();

    dim3 g1(II / BN, TT / BM, EE);   // (32, 128, 8)
    moe_gemm_kernel<true><<<g1, 256, SMEM_DYN>>>(b1, nullptr);

    cudaMemsetAsync(out, 0, (size_t)TT * HH * sizeof(float), 0);

    dim3 g2(HH / BN, TT / BM, EE);   // (8, 128, 8)
    moe_gemm_kernel<false><<<g2, 256, SMEM_DYN>>>(b2, out);
}

// round 9
// speedup vs baseline: 2.5749x; 1.0385x over previous
#include <cuda_runtime.h>
#include <cuda_fp16.h>
#include <cstdint>

// Problem constants
#define TT 16384   // B*S tokens
#define HH 1024    // hidden
#define II 4096    // intermediate
#define EE 8       // experts

// ---------------- scratch (device globals; no runtime allocation) ----------
__device__ int    d_counts[EE];
__device__ int    d_offsets[EE];
__device__ int    d_tok[EE * TT];
__device__ float  d_wt[EE * TT];
__device__ __half d_hmid[(size_t)2 * TT * II];    // fp16 intermediate (268 MB)
__device__ __half d_xh[(size_t)TT * HH];          // fp16 x (written by router)
__device__ __half d_w1h[(size_t)EE * II * HH];    // fp16 W1
__device__ __half d_w2h[(size_t)EE * HH * II];    // fp16 W2

// ---------------- helpers ----------------
__device__ __forceinline__ float silu_f(float v) { return v / (1.0f + __expf(-v)); }
__device__ __forceinline__ uint32_t smem_u32(const void* p) {
    uint32_t a;
    asm("{ .reg .u64 t; cvta.to.shared.u64 t, %1; cvt.u32.u64 %0, t; }" : "=r"(a) : "l"(p));
    return a;
}

#define MMA_F16(D, A, B_)                                                        \
    asm volatile(                                                                \
        "mma.sync.aligned.m16n8k16.row.col.f32.f16.f16.f32 "                     \
        "{%0,%1,%2,%3}, {%4,%5,%6,%7}, {%8,%9}, {%0,%1,%2,%3};\n"                \
        : "+f"((D)[0]), "+f"((D)[1]), "+f"((D)[2]), "+f"((D)[3])                 \
        : "r"((A)[0]), "r"((A)[1]), "r"((A)[2]), "r"((A)[3]),                    \
          "r"((B_)[0]), "r"((B_)[1]))

#define LDSM_X4(r0, r1, r2, r3, addr)                                            \
    asm volatile("ldmatrix.sync.aligned.m8n8.x4.shared.b16 {%0,%1,%2,%3}, [%4];" \
        : "=r"(r0), "=r"(r1), "=r"(r2), "=r"(r3) : "r"(addr))

#define CP_ASYNC16(saddr, gptr) \
    asm volatile("cp.async.cg.shared.global [%0], [%1], 16;" :: "r"(saddr), "l"(gptr) : "memory")
#define CP_COMMIT() asm volatile("cp.async.commit_group;" ::: "memory")
#define CP_WAIT2()  asm volatile("cp.async.wait_group 2;" ::: "memory")

// ---------------- kernel: fp32 -> fp16 weight conversion (+zero counters) --
__global__ __launch_bounds__(256)
void cvt_f16_kernel(const float4* __restrict__ src, int which, size_t n4) {
    if (which == 1 && blockIdx.x == 0 && threadIdx.x < EE)
        d_counts[threadIdx.x] = 0;
    __half* dstb = (which == 1) ? d_w1h : d_w2h;
    uint2* dst = (uint2*)dstb;
    size_t i  = (size_t)blockIdx.x * blockDim.x + threadIdx.x;
    size_t st = (size_t)gridDim.x * blockDim.x;
    for (; i < n4; i += st) {
        float4 v = src[i];
        __half2 h0 = __floats2half2_rn(v.x, v.y);
        __half2 h1 = __floats2half2_rn(v.z, v.w);
        uint2 o;
        o.x = *(uint32_t*)&h0;
        o.y = *(uint32_t*)&h1;
        dst[i] = o;
    }
}

// ---------------- kernel: router (fp32) + fused x->fp16 ----------------
__global__ __launch_bounds__(256)
void router_kernel(const float* __restrict__ x,
                   const float* __restrict__ Wg,
                   float* __restrict__ logits_out) {
    __shared__ float sWg[EE][HH];
    for (int i = threadIdx.x; i < EE * HH; i += blockDim.x)
        sWg[i / HH][i % HH] = Wg[i];
    __syncthreads();

    const int warp = threadIdx.x >> 5;
    const int lane = threadIdx.x & 31;
    const int t = blockIdx.x * 8 + warp;
    if (t >= TT) return;

    const float* xr = x + (size_t)t * HH;

    // fused x -> fp16 (vectorized; accumulation below keeps identical order)
    {
        uint2* xo = (uint2*)(d_xh + (size_t)t * HH);
        const float4* xi = (const float4*)xr;
        for (int k4 = lane; k4 < HH / 4; k4 += 32) {
            float4 v = xi[k4];
            __half2 h0 = __floats2half2_rn(v.x, v.y);
            __half2 h1 = __floats2half2_rn(v.z, v.w);
            uint2 o;
            o.x = *(uint32_t*)&h0;
            o.y = *(uint32_t*)&h1;
            xo[k4] = o;
        }
    }

    float acc[EE];
#pragma unroll
    for (int e = 0; e < EE; e++) acc[e] = 0.0f;
    for (int k = lane; k < HH; k += 32) {
        float xv = xr[k];
#pragma unroll
        for (int e = 0; e < EE; e++) acc[e] += xv * sWg[e][k];
    }
#pragma unroll
    for (int off = 16; off > 0; off >>= 1)
#pragma unroll
        for (int e = 0; e < EE; e++)
            acc[e] += __shfl_xor_sync(0xFFFFFFFFu, acc[e], off);

    if (lane == 0) {
        if (logits_out)
#pragma unroll
            for (int e = 0; e < EE; e++) logits_out[(size_t)t * EE + e] = acc[e];
        int i0 = 0; float v0 = acc[0];
#pragma unroll
        for (int e = 1; e < EE; e++) if (acc[e] > v0) { v0 = acc[e]; i0 = e; }
        int i1 = -1; float v1 = -3.4e38f;
#pragma unroll
        for (int e = 0; e < EE; e++)
            if (e != i0 && acc[e] > v1) { v1 = acc[e]; i1 = e; }
        float r  = expf(v1 - v0);
        float w0 = 1.0f / (1.0f + r);
        float w1 = 1.0f - w0;
        int p0 = atomicAdd(&d_counts[i0], 1);
        d_tok[i0 * TT + p0] = t;  d_wt[i0 * TT + p0] = w0;
        int p1 = atomicAdd(&d_counts[i1], 1);
        d_tok[i1 * TT + p1] = t;  d_wt[i1 * TT + p1] = w1;
    }
}

// ---------------- kernel: prefix scan ----------------
__global__ void scan_kernel() {
    int off = 0;
#pragma unroll
    for (int e = 0; e < EE; e++) { d_offsets[e] = off; off += d_counts[e]; }
}

// ---------------- GEMM: fp16 m16n8k16, 128x128 CTA, 4 warps, 2 CTAs/SM --
// 4 warps (2m x 2n), 64x64 per warp, ldmatrix loads, 4-stage cp.async.
constexpr int BM = 128, BN = 128, BK = 32;
constexpr int NT = 128;                            // threads per CTA
constexpr int BKW = 20;                            // padded words/row
constexpr int A_STAGE_B = BM * BKW * 4;            // 10240 B
constexpr int B_STAGE_B = BN * BKW * 4;            // 10240 B
constexpr int STAGE_B   = A_STAGE_B + B_STAGE_B;   // 20480 B
constexpr int NSTAGE    = 4;
constexpr int SMEM_DYN  = NSTAGE * STAGE_B;        // 81920 B (2 CTAs -> 160 KB/SM)

template <bool FIRST>
__global__ __launch_bounds__(NT, 2)
void moe_gemm_kernel(const float* __restrict__ bias, float* __restrict__ out) {
    const int e   = blockIdx.z;
    const int cnt = d_counts[e];
    const int m0  = blockIdx.y * BM;
    if (m0 >= cnt) return;
    const int n0   = blockIdx.x * BN;
    const int KDIM = FIRST ? HH : II;
    const int NDIM = FIRST ? II : HH;
    const int offs = d_offsets[e];
    const int NC   = KDIM / BK;

    extern __shared__ char dynsmem[];
    const uint32_t sbase = smem_u32(dynsmem);

    const int tid = threadIdx.x;
    const __half* Aglob = FIRST ? d_xh : d_hmid;
    const __half* Wt    = FIRST ? d_w1h : d_w2h;

    // cp.async loaders: A 4 chunks/thread, B 4 chunks/thread (16B each)
    const __half* aG[4]; uint32_t aSoff[4];
#pragma unroll
    for (int j = 0; j < 4; j++) {
        int idx = tid + j * NT;
        int row = idx >> 2, c = idx & 3;
        int gm = m0 + row;
        if (gm >= cnt) gm = cnt - 1;
        size_t rowoff;
        if (FIRST) rowoff = (size_t)d_tok[e * TT + gm] * HH;
        else       rowoff = (size_t)(offs + gm) * II;
        aG[j]    = Aglob + rowoff + c * 8;
        aSoff[j] = row * (BKW * 4) + c * 16;
    }
    const __half* bG[4]; uint32_t bSoff[4];
#pragma unroll
    for (int j = 0; j < 4; j++) {
        int idx = tid + j * NT;
        int row = idx >> 2, c = idx & 3;
        bG[j]    = Wt + (size_t)e * ((size_t)II * HH) + (size_t)(n0 + row) * KDIM + c * 8;
        bSoff[j] = A_STAGE_B + row * (BKW * 4) + c * 16;
    }

    // prologue: stages 0..2
#pragma unroll
    for (int s = 0; s < NSTAGE - 1; s++) {
        uint32_t so = sbase + s * STAGE_B;
#pragma unroll
        for (int j = 0; j < 4; j++) CP_ASYNC16(so + aSoff[j], aG[j] + s * BK);
#pragma unroll
        for (int j = 0; j < 4; j++) CP_ASYNC16(so + bSoff[j], bG[j] + s * BK);
        CP_COMMIT();
    }

    const int wid = tid >> 5, lane = tid & 31;
    const int wm = (wid >> 1) * 64;       // 2 m-warps
    const int wn = (wid & 1) * 64;        // 2 n-warps
    const int g = lane >> 2, tg = lane & 3;

    // ldmatrix per-lane base addresses: A 4 frags (m16k16), B 4 frags (n16k16)
    uint32_t aLd[4];
#pragma unroll
    for (int mf = 0; mf < 4; mf++) {
        int row = wm + mf * 16 + (lane & 7) + ((lane >> 3) & 1) * 8;
        int col = ((lane >> 4) & 1) * 16;
        aLd[mf] = sbase + row * (BKW * 4) + col;
    }
    uint32_t bLd[4];
#pragma unroll
    for (int nf2 = 0; nf2 < 4; nf2++) {
        int row = wn + nf2 * 16 + (lane & 7) + ((lane >> 4) & 1) * 8;
        int col = ((lane >> 3) & 1) * 16;
        bLd[nf2] = sbase + A_STAGE_B + row * (BKW * 4) + col;
    }

    float acc[4][8][4];
#pragma unroll
    for (int a = 0; a < 4; a++)
#pragma unroll
        for (int b = 0; b < 8; b++)
#pragma unroll
            for (int c = 0; c < 4; c++) acc[a][b][c] = 0.0f;

    int stage = 0;
    for (int i = 0; i < NC; i++) {
        CP_WAIT2();              // current stage resident; <=2 groups in flight
        __syncthreads();

        const int nx = i + NSTAGE - 1;
        if (nx < NC) {
            int s = nx & (NSTAGE - 1);
            uint32_t so = sbase + s * STAGE_B;
#pragma unroll
            for (int j = 0; j < 4; j++) CP_ASYNC16(so + aSoff[j], aG[j] + nx * BK);
#pragma unroll
            for (int j = 0; j < 4; j++) CP_ASYNC16(so + bSoff[j], bG[j] + nx * BK);
        }
        CP_COMMIT();

        const uint32_t stoff = stage * STAGE_B;
#pragma unroll
        for (int kk = 0; kk < 2; kk++) {
            const uint32_t ko = stoff + kk * 32;
            uint32_t af[4][4], bf[8][2];
#pragma unroll
            for (int mf = 0; mf < 4; mf++)
                LDSM_X4(af[mf][0], af[mf][1], af[mf][2], af[mf][3], aLd[mf] + ko);
#pragma unroll
            for (int nf2 = 0; nf2 < 4; nf2++)
                LDSM_X4(bf[nf2 * 2][0], bf[nf2 * 2][1],
                        bf[nf2 * 2 + 1][0], bf[nf2 * 2 + 1][1], bLd[nf2] + ko);
#pragma unroll
            for (int mf = 0; mf < 4; mf++)
#pragma unroll
                for (int nf = 0; nf < 8; nf++)
                    MMA_F16(acc[mf][nf], af[mf], bf[nf]);
        }
        stage = (stage + 1) & (NSTAGE - 1);
    }

    // epilogue (acc: d0,d1 = row g cols 2tg,2tg+1; d2,d3 = row g+8)
#pragma unroll
    for (int mf = 0; mf < 4; mf++) {
#pragma unroll
        for (int half = 0; half < 2; half++) {
            int m = m0 + wm + mf * 16 + g + half * 8;
            if (m >= cnt) continue;
            if (FIRST) {
                __half* dst = d_hmid + (size_t)(offs + m) * II + n0;
#pragma unroll
                for (int nf = 0; nf < 8; nf++) {
                    int col = wn + nf * 8 + tg * 2;
                    float bb0 = bias[(size_t)e * NDIM + n0 + col];
                    float bb1 = bias[(size_t)e * NDIM + n0 + col + 1];
                    float s0 = silu_f(acc[mf][nf][half * 2 + 0] + bb0);
                    float s1 = silu_f(acc[mf][nf][half * 2 + 1] + bb1);
                    *(__half2*)(dst + col) = __floats2half2_rn(s0, s1);
                }
            } else {
                int tok = d_tok[e * TT + m];
                float w = d_wt[e * TT + m];
                float* dst = out + (size_t)tok * HH + n0;
#pragma unroll
                for (int nf = 0; nf < 8; nf++) {
                    int col = wn + nf * 8 + tg * 2;
                    float bb0 = bias[(size_t)e * NDIM + n0 + col];
                    float bb1 = bias[(size_t)e * NDIM + n0 + col + 1];
                    atomicAdd(dst + col,     w * (acc[mf][nf][half * 2 + 0] + bb0));
                    atomicAdd(dst + col + 1, w * (acc[mf][nf][half * 2 + 1] + bb1));
                }
            }
        }
    }
}

// ---------------- launch ----------------
extern "C" void kernel_launch(void* const* d_in, const int* in_sizes, int n_in,
                              void* d_out, int out_size) {
    const float* x  = (const float*)d_in[0];   // [T,H]
    const float* Wg = (const float*)d_in[1];   // [E,H]
    const float* W1 = (const float*)d_in[2];   // [E,I,H]
    const float* b1 = (const float*)d_in[3];   // [E,I]
    const float* W2 = (const float*)d_in[4];   // [E,H,I]
    const float* b2 = (const float*)d_in[5];   // [E,H]
    float* out = (float*)d_out;

    float* logits = nullptr;
    if ((size_t)out_size >= (size_t)TT * HH + (size_t)TT * EE)
        logits = out + (size_t)TT * HH;

    cudaFuncSetAttribute(moe_gemm_kernel<true>,  cudaFuncAttributeMaxDynamicSharedMemorySize, SMEM_DYN);
    cudaFuncSetAttribute(moe_gemm_kernel<false>, cudaFuncAttributeMaxDynamicSharedMemorySize, SMEM_DYN);

    cvt_f16_kernel<<<4096, 256>>>((const float4*)W1, 1, (size_t)EE * II * HH / 4);  // zeroes counts
    cvt_f16_kernel<<<4096, 256>>>((const float4*)W2, 2, (size_t)EE * HH * II / 4);
    router_kernel<<<TT / 8, 256>>>(x, Wg, logits);   // also writes d_xh
    scan_kernel<<<1, 1>>>();

    dim3 g1(II / BN, TT / BM, EE);   // (32, 128, 8)
    moe_gemm_kernel<true><<<g1, NT, SMEM_DYN>>>(b1, nullptr);

    cudaMemsetAsync(out, 0, (size_t)TT * HH * sizeof(float), 0);

    dim3 g2(HH / BN, TT / BM, EE);   // (8, 128, 8)
    moe_gemm_kernel<false><<<g2, NT, SMEM_DYN>>>(b2, out);
}

// round 10
// speedup vs baseline: 2.5976x; 1.0088x over previous
#include <cuda_runtime.h>
#include <cuda_fp16.h>
#include <cstdint>

// Problem constants
#define TT 16384   // B*S tokens
#define HH 1024    // hidden
#define II 4096    // intermediate
#define EE 8       // experts

// ---------------- scratch (device globals; no runtime allocation) ----------
__device__ int      d_counts[EE];
__device__ int      d_tok[EE * TT];
__device__ float    d_wt[EE * TT];
__device__ uint32_t d_slotEP[2 * TT];             // (expert<<20)|pos per token slot
__device__ float    d_wtok[2 * TT];               // per-token top-2 weights
__device__ __half   d_hmid[(size_t)2 * TT * II];  // fp16 intermediate (268 MB)
__device__ float    d_osc[(size_t)2 * TT * HH];   // fp32 expert outputs (134 MB)
__device__ __half   d_xh[(size_t)TT * HH];        // fp16 x (written by router)
__device__ __half   d_w1h[(size_t)EE * II * HH];  // fp16 W1
__device__ __half   d_w2h[(size_t)EE * HH * II];  // fp16 W2

// ---------------- helpers ----------------
__device__ __forceinline__ float silu_f(float v) { return v / (1.0f + __expf(-v)); }
__device__ __forceinline__ uint32_t smem_u32(const void* p) {
    uint32_t a;
    asm("{ .reg .u64 t; cvta.to.shared.u64 t, %1; cvt.u32.u64 %0, t; }" : "=r"(a) : "l"(p));
    return a;
}
// inline exclusive prefix over the 8 counts
__device__ __forceinline__ int expert_offset(int e) {
    int off = 0;
#pragma unroll
    for (int q = 0; q < EE; q++) off += (q < e) ? d_counts[q] : 0;
    return off;
}

#define MMA_F16(D, A, B_)                                                        \
    asm volatile(                                                                \
        "mma.sync.aligned.m16n8k16.row.col.f32.f16.f16.f32 "                     \
        "{%0,%1,%2,%3}, {%4,%5,%6,%7}, {%8,%9}, {%0,%1,%2,%3};\n"                \
        : "+f"((D)[0]), "+f"((D)[1]), "+f"((D)[2]), "+f"((D)[3])                 \
        : "r"((A)[0]), "r"((A)[1]), "r"((A)[2]), "r"((A)[3]),                    \
          "r"((B_)[0]), "r"((B_)[1]))

#define LDSM_X4(r0, r1, r2, r3, addr)                                            \
    asm volatile("ldmatrix.sync.aligned.m8n8.x4.shared.b16 {%0,%1,%2,%3}, [%4];" \
        : "=r"(r0), "=r"(r1), "=r"(r2), "=r"(r3) : "r"(addr))

#define CP_ASYNC16(saddr, gptr) \
    asm volatile("cp.async.cg.shared.global [%0], [%1], 16;" :: "r"(saddr), "l"(gptr) : "memory")
#define CP_COMMIT() asm volatile("cp.async.commit_group;" ::: "memory")
#define CP_WAIT2()  asm volatile("cp.async.wait_group 2;" ::: "memory")

// ---------------- kernel: fp32 -> fp16 weight conversion (+zero counters) --
__global__ __launch_bounds__(256)
void cvt_f16_kernel(const float4* __restrict__ src, int which, size_t n4) {
    if (which == 1 && blockIdx.x == 0 && threadIdx.x < EE)
        d_counts[threadIdx.x] = 0;
    __half* dstb = (which == 1) ? d_w1h : d_w2h;
    uint2* dst = (uint2*)dstb;
    size_t i  = (size_t)blockIdx.x * blockDim.x + threadIdx.x;
    size_t st = (size_t)gridDim.x * blockDim.x;
    for (; i < n4; i += st) {
        float4 v = src[i];
        __half2 h0 = __floats2half2_rn(v.x, v.y);
        __half2 h1 = __floats2half2_rn(v.z, v.w);
        uint2 o;
        o.x = *(uint32_t*)&h0;
        o.y = *(uint32_t*)&h1;
        dst[i] = o;
    }
}

// ---------------- kernel: router (fp32) + fused x->fp16 + slot record ------
__global__ __launch_bounds__(256)
void router_kernel(const float* __restrict__ x,
                   const float* __restrict__ Wg,
                   float* __restrict__ logits_out) {
    __shared__ float sWg[EE][HH];
    for (int i = threadIdx.x; i < EE * HH; i += blockDim.x)
        sWg[i / HH][i % HH] = Wg[i];
    __syncthreads();

    const int warp = threadIdx.x >> 5;
    const int lane = threadIdx.x & 31;
    const int t = blockIdx.x * 8 + warp;
    if (t >= TT) return;

    const float* xr = x + (size_t)t * HH;

    // fused x -> fp16
    {
        uint2* xo = (uint2*)(d_xh + (size_t)t * HH);
        const float4* xi = (const float4*)xr;
        for (int k4 = lane; k4 < HH / 4; k4 += 32) {
            float4 v = xi[k4];
            __half2 h0 = __floats2half2_rn(v.x, v.y);
            __half2 h1 = __floats2half2_rn(v.z, v.w);
            uint2 o;
            o.x = *(uint32_t*)&h0;
            o.y = *(uint32_t*)&h1;
            xo[k4] = o;
        }
    }

    float acc[EE];
#pragma unroll
    for (int e = 0; e < EE; e++) acc[e] = 0.0f;
    for (int k = lane; k < HH; k += 32) {
        float xv = xr[k];
#pragma unroll
        for (int e = 0; e < EE; e++) acc[e] += xv * sWg[e][k];
    }
#pragma unroll
    for (int off = 16; off > 0; off >>= 1)
#pragma unroll
        for (int e = 0; e < EE; e++)
            acc[e] += __shfl_xor_sync(0xFFFFFFFFu, acc[e], off);

    if (lane == 0) {
        if (logits_out)
#pragma unroll
            for (int e = 0; e < EE; e++) logits_out[(size_t)t * EE + e] = acc[e];
        int i0 = 0; float v0 = acc[0];
#pragma unroll
        for (int e = 1; e < EE; e++) if (acc[e] > v0) { v0 = acc[e]; i0 = e; }
        int i1 = -1; float v1 = -3.4e38f;
#pragma unroll
        for (int e = 0; e < EE; e++)
            if (e != i0 && acc[e] > v1) { v1 = acc[e]; i1 = e; }
        float r  = expf(v1 - v0);
        float w0 = 1.0f / (1.0f + r);
        float w1 = 1.0f - w0;
        int p0 = atomicAdd(&d_counts[i0], 1);
        d_tok[i0 * TT + p0] = t;
        d_wt[i0 * TT + p0] = w0;
        int p1 = atomicAdd(&d_counts[i1], 1);
        d_tok[i1 * TT + p1] = t;
        d_wt[i1 * TT + p1] = w1;
        d_slotEP[t * 2 + 0] = ((uint32_t)i0 << 20) | (uint32_t)p0;
        d_slotEP[t * 2 + 1] = ((uint32_t)i1 << 20) | (uint32_t)p1;
        d_wtok[t * 2 + 0] = w0;
        d_wtok[t * 2 + 1] = w1;
    }
}

// ---------------- GEMM: fp16 m16n8k16, 128x128 CTA, 4 warps, 2 CTAs/SM --
// 4 warps (2m x 2n), 64x64 per warp, ldmatrix loads, 4-stage cp.async.
constexpr int BM = 128, BN = 128, BK = 32;
constexpr int NT = 128;                            // threads per CTA
constexpr int BKW = 20;                            // padded words/row
constexpr int A_STAGE_B = BM * BKW * 4;            // 10240 B
constexpr int B_STAGE_B = BN * BKW * 4;            // 10240 B
constexpr int STAGE_B   = A_STAGE_B + B_STAGE_B;   // 20480 B
constexpr int NSTAGE    = 4;
constexpr int SMEM_DYN  = NSTAGE * STAGE_B;        // 81920 B (2 CTAs -> 160 KB/SM)

template <bool FIRST>
__global__ __launch_bounds__(NT, 2)
void moe_gemm_kernel(const float* __restrict__ bias) {
    const int e   = blockIdx.z;
    const int cnt = d_counts[e];
    const int m0  = blockIdx.y * BM;
    if (m0 >= cnt) return;
    const int n0   = blockIdx.x * BN;
    const int KDIM = FIRST ? HH : II;
    const int NDIM = FIRST ? II : HH;
    const int offs = expert_offset(e);
    const int NC   = KDIM / BK;

    extern __shared__ char dynsmem[];
    const uint32_t sbase = smem_u32(dynsmem);

    const int tid = threadIdx.x;
    const __half* Aglob = FIRST ? d_xh : d_hmid;
    const __half* Wt    = FIRST ? d_w1h : d_w2h;

    // cp.async loaders: A 4 chunks/thread, B 4 chunks/thread (16B each)
    const __half* aG[4]; uint32_t aSoff[4];
#pragma unroll
    for (int j = 0; j < 4; j++) {
        int idx = tid + j * NT;
        int row = idx >> 2, c = idx & 3;
        int gm = m0 + row;
        if (gm >= cnt) gm = cnt - 1;
        size_t rowoff;
        if (FIRST) rowoff = (size_t)d_tok[e * TT + gm] * HH;
        else       rowoff = (size_t)(offs + gm) * II;
        aG[j]    = Aglob + rowoff + c * 8;
        aSoff[j] = row * (BKW * 4) + c * 16;
    }
    const __half* bG[4]; uint32_t bSoff[4];
#pragma unroll
    for (int j = 0; j < 4; j++) {
        int idx = tid + j * NT;
        int row = idx >> 2, c = idx & 3;
        bG[j]    = Wt + (size_t)e * ((size_t)II * HH) + (size_t)(n0 + row) * KDIM + c * 8;
        bSoff[j] = A_STAGE_B + row * (BKW * 4) + c * 16;
    }

    // prologue: stages 0..2
#pragma unroll
    for (int s = 0; s < NSTAGE - 1; s++) {
        uint32_t so = sbase + s * STAGE_B;
#pragma unroll
        for (int j = 0; j < 4; j++) CP_ASYNC16(so + aSoff[j], aG[j] + s * BK);
#pragma unroll
        for (int j = 0; j < 4; j++) CP_ASYNC16(so + bSoff[j], bG[j] + s * BK);
        CP_COMMIT();
    }

    const int wid = tid >> 5, lane = tid & 31;
    const int wm = (wid >> 1) * 64;       // 2 m-warps
    const int wn = (wid & 1) * 64;        // 2 n-warps
    const int g = lane >> 2, tg = lane & 3;

    // ldmatrix per-lane base addresses: A 4 frags (m16k16), B 4 frags (n16k16)
    uint32_t aLd[4];
#pragma unroll
    for (int mf = 0; mf < 4; mf++) {
        int row = wm + mf * 16 + (lane & 7) + ((lane >> 3) & 1) * 8;
        int col = ((lane >> 4) & 1) * 16;
        aLd[mf] = sbase + row * (BKW * 4) + col;
    }
    uint32_t bLd[4];
#pragma unroll
    for (int nf2 = 0; nf2 < 4; nf2++) {
        int row = wn + nf2 * 16 + (lane & 7) + ((lane >> 4) & 1) * 8;
        int col = ((lane >> 3) & 1) * 16;
        bLd[nf2] = sbase + A_STAGE_B + row * (BKW * 4) + col;
    }

    float acc[4][8][4];
#pragma unroll
    for (int a = 0; a < 4; a++)
#pragma unroll
        for (int b = 0; b < 8; b++)
#pragma unroll
            for (int c = 0; c < 4; c++) acc[a][b][c] = 0.0f;

    int stage = 0;
    for (int i = 0; i < NC; i++) {
        CP_WAIT2();              // current stage resident; <=2 groups in flight
        __syncthreads();

        const int nx = i + NSTAGE - 1;
        if (nx < NC) {
            int s = nx & (NSTAGE - 1);
            uint32_t so = sbase + s * STAGE_B;
#pragma unroll
            for (int j = 0; j < 4; j++) CP_ASYNC16(so + aSoff[j], aG[j] + nx * BK);
#pragma unroll
            for (int j = 0; j < 4; j++) CP_ASYNC16(so + bSoff[j], bG[j] + nx * BK);
        }
        CP_COMMIT();

        const uint32_t stoff = stage * STAGE_B;
#pragma unroll
        for (int kk = 0; kk < 2; kk++) {
            const uint32_t ko = stoff + kk * 32;
            uint32_t af[4][4], bf[8][2];
#pragma unroll
            for (int mf = 0; mf < 4; mf++)
                LDSM_X4(af[mf][0], af[mf][1], af[mf][2], af[mf][3], aLd[mf] + ko);
#pragma unroll
            for (int nf2 = 0; nf2 < 4; nf2++)
                LDSM_X4(bf[nf2 * 2][0], bf[nf2 * 2][1],
                        bf[nf2 * 2 + 1][0], bf[nf2 * 2 + 1][1], bLd[nf2] + ko);
#pragma unroll
            for (int mf = 0; mf < 4; mf++)
#pragma unroll
                for (int nf = 0; nf < 8; nf++)
                    MMA_F16(acc[mf][nf], af[mf], bf[nf]);
        }
        stage = (stage + 1) & (NSTAGE - 1);
    }

    // epilogue (acc: d0,d1 = row g cols 2tg,2tg+1; d2,d3 = row g+8)
#pragma unroll
    for (int mf = 0; mf < 4; mf++) {
#pragma unroll
        for (int half = 0; half < 2; half++) {
            int m = m0 + wm + mf * 16 + g + half * 8;
            if (m >= cnt) continue;
            if (FIRST) {
                __half* dst = d_hmid + (size_t)(offs + m) * II + n0;
#pragma unroll
                for (int nf = 0; nf < 8; nf++) {
                    int col = wn + nf * 8 + tg * 2;
                    float bb0 = bias[(size_t)e * NDIM + n0 + col];
                    float bb1 = bias[(size_t)e * NDIM + n0 + col + 1];
                    float s0 = silu_f(acc[mf][nf][half * 2 + 0] + bb0);
                    float s1 = silu_f(acc[mf][nf][half * 2 + 1] + bb1);
                    *(__half2*)(dst + col) = __floats2half2_rn(s0, s1);
                }
            } else {
                float* dst = d_osc + (size_t)(offs + m) * HH + n0;
#pragma unroll
                for (int nf = 0; nf < 8; nf++) {
                    int col = wn + nf * 8 + tg * 2;
                    float bb0 = bias[(size_t)e * NDIM + n0 + col];
                    float bb1 = bias[(size_t)e * NDIM + n0 + col + 1];
                    *(float2*)(dst + col) = make_float2(acc[mf][nf][half * 2 + 0] + bb0,
                                                        acc[mf][nf][half * 2 + 1] + bb1);
                }
            }
        }
    }
}

// ---------------- kernel: combine two expert rows per token ----------------
__global__ __launch_bounds__(256)
void combine_kernel(float* __restrict__ out) {
    const int t = blockIdx.x;
    const uint32_t s0 = d_slotEP[t * 2 + 0];
    const uint32_t s1 = d_slotEP[t * 2 + 1];
    const int e0 = (int)(s0 >> 20), p0 = (int)(s0 & 0xFFFFFu);
    const int e1 = (int)(s1 >> 20), p1 = (int)(s1 & 0xFFFFFu);
    const float w0 = d_wtok[t * 2 + 0];
    const float w1 = d_wtok[t * 2 + 1];
    const size_t r0 = (size_t)(expert_offset(e0) + p0) * HH;
    const size_t r1 = (size_t)(expert_offset(e1) + p1) * HH;
    const float4* a = (const float4*)(d_osc + r0);
    const float4* b = (const float4*)(d_osc + r1);
    float4* o = (float4*)(out + (size_t)t * HH);
    const int k = threadIdx.x;           // 256 threads x float4 = 1024
    float4 va = a[k], vb = b[k];
    float4 vo;
    vo.x = w0 * va.x + w1 * vb.x;
    vo.y = w0 * va.y + w1 * vb.y;
    vo.z = w0 * va.z + w1 * vb.z;
    vo.w = w0 * va.w + w1 * vb.w;
    o[k] = vo;
}

// ---------------- launch ----------------
extern "C" void kernel_launch(void* const* d_in, const int* in_sizes, int n_in,
                              void* d_out, int out_size) {
    const float* x  = (const float*)d_in[0];   // [T,H]
    const float* Wg = (const float*)d_in[1];   // [E,H]
    const float* W1 = (const float*)d_in[2];   // [E,I,H]
    const float* b1 = (const float*)d_in[3];   // [E,I]
    const float* W2 = (const float*)d_in[4];   // [E,H,I]
    const float* b2 = (const float*)d_in[5];   // [E,H]
    float* out = (float*)d_out;

    float* logits = nullptr;
    if ((size_t)out_size >= (size_t)TT * HH + (size_t)TT * EE)
        logits = out + (size_t)TT * HH;

    cudaFuncSetAttribute(moe_gemm_kernel<true>,  cudaFuncAttributeMaxDynamicSharedMemorySize, SMEM_DYN);
    cudaFuncSetAttribute(moe_gemm_kernel<false>, cudaFuncAttributeMaxDynamicSharedMemorySize, SMEM_DYN);

    cvt_f16_kernel<<<4096, 256>>>((const float4*)W1, 1, (size_t)EE * II * HH / 4);  // zeroes counts
    cvt_f16_kernel<<<4096, 256>>>((const float4*)W2, 2, (size_t)EE * HH * II / 4);
    router_kernel<<<TT / 8, 256>>>(x, Wg, logits);   // also writes d_xh + slots

    dim3 g1(II / BN, TT / BM, EE);   // (32, 128, 8) -- 4th launch: ncu profiles this
    moe_gemm_kernel<true><<<g1, NT, SMEM_DYN>>>(b1);

    dim3 g2(HH / BN, TT / BM, EE);   // (8, 128, 8)
    moe_gemm_kernel<false><<<g2, NT, SMEM_DYN>>>(b2);

    combine_kernel<<<TT, 256>>>(out);
}

// round 11
// speedup vs baseline: 2.7165x; 1.0458x over previous
#include <cuda_runtime.h>
#include <cuda_fp16.h>
#include <cstdint>

// Problem constants
#define TT 16384   // B*S tokens
#define HH 1024    // hidden
#define II 4096    // intermediate
#define EE 8       // experts

// ---------------- scratch (device globals; no runtime allocation) ----------
__device__ int      d_counts[EE];
__device__ int      d_tok[EE * TT];
__device__ uint32_t d_slotEP[2 * TT];             // (expert<<20)|pos per token slot
__device__ float    d_wtok[2 * TT];               // per-token top-2 weights
__device__ __half   d_hmid[(size_t)2 * TT * II];  // fp16 intermediate (268 MB)
__device__ float    d_osc[(size_t)2 * TT * HH];   // fp32 expert outputs (134 MB)
__device__ __half   d_xh[(size_t)TT * HH];        // fp16 x (written by router)
__device__ __half   d_w1h[(size_t)EE * II * HH];  // fp16 W1
__device__ __half   d_w2h[(size_t)EE * HH * II];  // fp16 W2

// ---------------- helpers ----------------
__device__ __forceinline__ float silu_f(float v) { return v / (1.0f + __expf(-v)); }
__device__ __forceinline__ uint32_t smem_u32(const void* p) {
    uint32_t a;
    asm("{ .reg .u64 t; cvta.to.shared.u64 t, %1; cvt.u32.u64 %0, t; }" : "=r"(a) : "l"(p));
    return a;
}
__device__ __forceinline__ int expert_offset(int e) {
    int off = 0;
#pragma unroll
    for (int q = 0; q < EE; q++) off += (q < e) ? d_counts[q] : 0;
    return off;
}

#define MMA_F16(D, A, B_)                                                        \
    asm volatile(                                                                \
        "mma.sync.aligned.m16n8k16.row.col.f32.f16.f16.f32 "                     \
        "{%0,%1,%2,%3}, {%4,%5,%6,%7}, {%8,%9}, {%0,%1,%2,%3};\n"                \
        : "+f"((D)[0]), "+f"((D)[1]), "+f"((D)[2]), "+f"((D)[3])                 \
        : "r"((A)[0]), "r"((A)[1]), "r"((A)[2]), "r"((A)[3]),                    \
          "r"((B_)[0]), "r"((B_)[1]))

#define LDSM_X4(r0, r1, r2, r3, addr)                                            \
    asm volatile("ldmatrix.sync.aligned.m8n8.x4.shared.b16 {%0,%1,%2,%3}, [%4];" \
        : "=r"(r0), "=r"(r1), "=r"(r2), "=r"(r3) : "r"(addr))

#define CP_ASYNC16(saddr, gptr) \
    asm volatile("cp.async.cg.shared.global [%0], [%1], 16;" :: "r"(saddr), "l"(gptr) : "memory")
#define CP_COMMIT() asm volatile("cp.async.commit_group;" ::: "memory")
#define CP_WAIT2()  asm volatile("cp.async.wait_group 2;" ::: "memory")

// ---------------- kernel: fp32 -> fp16 weight conversion (+zero counters) --
__global__ __launch_bounds__(256)
void cvt_f16_kernel(const float4* __restrict__ src, int which, size_t n4) {
    if (which == 1 && blockIdx.x == 0 && threadIdx.x < EE)
        d_counts[threadIdx.x] = 0;
    __half* dstb = (which == 1) ? d_w1h : d_w2h;
    uint2* dst = (uint2*)dstb;
    size_t i  = (size_t)blockIdx.x * blockDim.x + threadIdx.x;
    size_t st = (size_t)gridDim.x * blockDim.x;
    for (; i < n4; i += st) {
        float4 v = src[i];
        __half2 h0 = __floats2half2_rn(v.x, v.y);
        __half2 h1 = __floats2half2_rn(v.z, v.w);
        uint2 o;
        o.x = *(uint32_t*)&h0;
        o.y = *(uint32_t*)&h1;
        dst[i] = o;
    }
}

// ---------------- kernel: router (fp32) + fused x->fp16 + slot record ------
__global__ __launch_bounds__(256)
void router_kernel(const float* __restrict__ x,
                   const float* __restrict__ Wg,
                   float* __restrict__ logits_out) {
    __shared__ float sWg[EE][HH];
    for (int i = threadIdx.x; i < EE * HH; i += blockDim.x)
        sWg[i / HH][i % HH] = Wg[i];
    __syncthreads();

    const int warp = threadIdx.x >> 5;
    const int lane = threadIdx.x & 31;
    const int t = blockIdx.x * 8 + warp;
    if (t >= TT) return;

    const float* xr = x + (size_t)t * HH;

    // fused x -> fp16
    {
        uint2* xo = (uint2*)(d_xh + (size_t)t * HH);
        const float4* xi = (const float4*)xr;
        for (int k4 = lane; k4 < HH / 4; k4 += 32) {
            float4 v = xi[k4];
            __half2 h0 = __floats2half2_rn(v.x, v.y);
            __half2 h1 = __floats2half2_rn(v.z, v.w);
            uint2 o;
            o.x = *(uint32_t*)&h0;
            o.y = *(uint32_t*)&h1;
            xo[k4] = o;
        }
    }

    float acc[EE];
#pragma unroll
    for (int e = 0; e < EE; e++) acc[e] = 0.0f;
    for (int k = lane; k < HH; k += 32) {
        float xv = xr[k];
#pragma unroll
        for (int e = 0; e < EE; e++) acc[e] += xv * sWg[e][k];
    }
#pragma unroll
    for (int off = 16; off > 0; off >>= 1)
#pragma unroll
        for (int e = 0; e < EE; e++)
            acc[e] += __shfl_xor_sync(0xFFFFFFFFu, acc[e], off);

    if (lane == 0) {
        if (logits_out)
#pragma unroll
            for (int e = 0; e < EE; e++) logits_out[(size_t)t * EE + e] = acc[e];
        int i0 = 0; float v0 = acc[0];
#pragma unroll
        for (int e = 1; e < EE; e++) if (acc[e] > v0) { v0 = acc[e]; i0 = e; }
        int i1 = -1; float v1 = -3.4e38f;
#pragma unroll
        for (int e = 0; e < EE; e++)
            if (e != i0 && acc[e] > v1) { v1 = acc[e]; i1 = e; }
        float r  = expf(v1 - v0);
        float w0 = 1.0f / (1.0f + r);
        float w1 = 1.0f - w0;
        int p0 = atomicAdd(&d_counts[i0], 1);
        d_tok[i0 * TT + p0] = t;
        int p1 = atomicAdd(&d_counts[i1], 1);
        d_tok[i1 * TT + p1] = t;
        d_slotEP[t * 2 + 0] = ((uint32_t)i0 << 20) | (uint32_t)p0;
        d_slotEP[t * 2 + 1] = ((uint32_t)i1 << 20) | (uint32_t)p1;
        d_wtok[t * 2 + 0] = w0;
        d_wtok[t * 2 + 1] = w1;
    }
}

// ---------------- GEMM: fp16 m16n8k16, 128x128 CTA, 4 warps, 2 CTAs/SM --
// 4 warps (2m x 2n), 64x64 per warp, double-buffered ldmatrix fragments,
// 4-stage cp.async.
constexpr int BM = 128, BN = 128, BK = 32;
constexpr int NT = 128;                            // threads per CTA
constexpr int BKW = 20;                            // padded words/row
constexpr int A_STAGE_B = BM * BKW * 4;            // 10240 B
constexpr int B_STAGE_B = BN * BKW * 4;            // 10240 B
constexpr int STAGE_B   = A_STAGE_B + B_STAGE_B;   // 20480 B
constexpr int NSTAGE    = 4;
constexpr int SMEM_DYN  = NSTAGE * STAGE_B;        // 81920 B (2 CTAs -> 160 KB/SM)

__device__ __forceinline__ void load_frags(uint32_t af[4][4], uint32_t bf[8][2],
                                           const uint32_t aLd[4], const uint32_t bLd[4],
                                           uint32_t ko) {
#pragma unroll
    for (int mf = 0; mf < 4; mf++)
        LDSM_X4(af[mf][0], af[mf][1], af[mf][2], af[mf][3], aLd[mf] + ko);
#pragma unroll
    for (int j = 0; j < 4; j++)
        LDSM_X4(bf[2 * j][0], bf[2 * j][1], bf[2 * j + 1][0], bf[2 * j + 1][1],
                bLd[j] + ko);
}

__device__ __forceinline__ void mma_all(float acc[4][8][4],
                                        const uint32_t af[4][4],
                                        const uint32_t bf[8][2]) {
#pragma unroll
    for (int mf = 0; mf < 4; mf++)
#pragma unroll
        for (int nf = 0; nf < 8; nf++)
            MMA_F16(acc[mf][nf], af[mf], bf[nf]);
}

template <bool FIRST>
__global__ __launch_bounds__(NT, 2)
void moe_gemm_kernel(const float* __restrict__ bias) {
    const int e   = blockIdx.z;
    const int cnt = d_counts[e];
    const int m0  = blockIdx.y * BM;
    if (m0 >= cnt) return;
    const int n0   = blockIdx.x * BN;
    const int KDIM = FIRST ? HH : II;
    const int NDIM = FIRST ? II : HH;
    const int offs = expert_offset(e);
    const int NC   = KDIM / BK;

    extern __shared__ char dynsmem[];
    const uint32_t sbase = smem_u32(dynsmem);

    const int tid = threadIdx.x;
    const __half* Aglob = FIRST ? d_xh : d_hmid;
    const __half* Wt    = FIRST ? d_w1h : d_w2h;

    // cp.async loaders: A 4 chunks/thread, B 4 chunks/thread (16B each)
    const __half* aG[4]; uint32_t aSoff[4];
#pragma unroll
    for (int j = 0; j < 4; j++) {
        int idx = tid + j * NT;
        int row = idx >> 2, c = idx & 3;
        int gm = m0 + row;
        if (gm >= cnt) gm = cnt - 1;
        size_t rowoff;
        if (FIRST) rowoff = (size_t)d_tok[e * TT + gm] * HH;
        else       rowoff = (size_t)(offs + gm) * II;
        aG[j]    = Aglob + rowoff + c * 8;
        aSoff[j] = row * (BKW * 4) + c * 16;
    }
    const __half* bG[4]; uint32_t bSoff[4];
#pragma unroll
    for (int j = 0; j < 4; j++) {
        int idx = tid + j * NT;
        int row = idx >> 2, c = idx & 3;
        bG[j]    = Wt + (size_t)e * ((size_t)II * HH) + (size_t)(n0 + row) * KDIM + c * 8;
        bSoff[j] = A_STAGE_B + row * (BKW * 4) + c * 16;
    }

    // prologue: stages 0..2
#pragma unroll
    for (int s = 0; s < NSTAGE - 1; s++) {
        uint32_t so = sbase + s * STAGE_B;
#pragma unroll
        for (int j = 0; j < 4; j++) CP_ASYNC16(so + aSoff[j], aG[j] + s * BK);
#pragma unroll
        for (int j = 0; j < 4; j++) CP_ASYNC16(so + bSoff[j], bG[j] + s * BK);
        CP_COMMIT();
    }

    const int wid = tid >> 5, lane = tid & 31;
    const int wm = (wid >> 1) * 64;       // 2 m-warps
    const int wn = (wid & 1) * 64;        // 2 n-warps
    const int g = lane >> 2, tg = lane & 3;

    // ldmatrix per-lane base addresses
    uint32_t aLd[4];
#pragma unroll
    for (int mf = 0; mf < 4; mf++) {
        int row = wm + mf * 16 + (lane & 7) + ((lane >> 3) & 1) * 8;
        int col = ((lane >> 4) & 1) * 16;
        aLd[mf] = sbase + row * (BKW * 4) + col;
    }
    uint32_t bLd[4];
#pragma unroll
    for (int nf2 = 0; nf2 < 4; nf2++) {
        int row = wn + nf2 * 16 + (lane & 7) + ((lane >> 4) & 1) * 8;
        int col = ((lane >> 3) & 1) * 16;
        bLd[nf2] = sbase + A_STAGE_B + row * (BKW * 4) + col;
    }

    float acc[4][8][4];
#pragma unroll
    for (int a = 0; a < 4; a++)
#pragma unroll
        for (int b = 0; b < 8; b++)
#pragma unroll
            for (int c = 0; c < 4; c++) acc[a][b][c] = 0.0f;

    // software-pipelined fragments: cur = kk0 of chunk i, nxt = kk1
    uint32_t afc[4][4], bfc[8][2], afn[4][4], bfn[8][2];

    CP_WAIT2();
    __syncthreads();
    load_frags(afc, bfc, aLd, bLd, 0u);        // chunk 0, kk0

    int stage = 0;
    for (int i = 0; i < NC; i++) {
        const uint32_t stoff = stage * STAGE_B;

        load_frags(afn, bfn, aLd, bLd, stoff + 32);   // kk1 of chunk i
        mma_all(acc, afc, bfc);                       // kk0 of chunk i

        const int nx = i + NSTAGE - 1;                // prefetch chunk i+3
        if (nx < NC) {
            int s = nx & (NSTAGE - 1);
            uint32_t so = sbase + s * STAGE_B;
#pragma unroll
            for (int j = 0; j < 4; j++) CP_ASYNC16(so + aSoff[j], aG[j] + nx * BK);
#pragma unroll
            for (int j = 0; j < 4; j++) CP_ASYNC16(so + bSoff[j], bG[j] + nx * BK);
        }
        CP_COMMIT();

        if (i + 1 < NC) {
            CP_WAIT2();
            __syncthreads();
            load_frags(afc, bfc, aLd, bLd, ((stage + 1) & (NSTAGE - 1)) * STAGE_B);
        }
        mma_all(acc, afn, bfn);                       // kk1 of chunk i
        stage = (stage + 1) & (NSTAGE - 1);
    }

    // epilogue (acc: d0,d1 = row g cols 2tg,2tg+1; d2,d3 = row g+8)
#pragma unroll
    for (int mf = 0; mf < 4; mf++) {
#pragma unroll
        for (int half = 0; half < 2; half++) {
            int m = m0 + wm + mf * 16 + g + half * 8;
            if (m >= cnt) continue;
            if (FIRST) {
                __half* dst = d_hmid + (size_t)(offs + m) * II + n0;
#pragma unroll
                for (int nf = 0; nf < 8; nf++) {
                    int col = wn + nf * 8 + tg * 2;
                    float bb0 = bias[(size_t)e * NDIM + n0 + col];
                    float bb1 = bias[(size_t)e * NDIM + n0 + col + 1];
                    float s0 = silu_f(acc[mf][nf][half * 2 + 0] + bb0);
                    float s1 = silu_f(acc[mf][nf][half * 2 + 1] + bb1);
                    *(__half2*)(dst + col) = __floats2half2_rn(s0, s1);
                }
            } else {
                float* dst = d_osc + (size_t)(offs + m) * HH + n0;
#pragma unroll
                for (int nf = 0; nf < 8; nf++) {
                    int col = wn + nf * 8 + tg * 2;
                    float bb0 = bias[(size_t)e * NDIM + n0 + col];
                    float bb1 = bias[(size_t)e * NDIM + n0 + col + 1];
                    *(float2*)(dst + col) = make_float2(acc[mf][nf][half * 2 + 0] + bb0,
                                                        acc[mf][nf][half * 2 + 1] + bb1);
                }
            }
        }
    }
}

// ---------------- kernel: combine two expert rows per token ----------------
__global__ __launch_bounds__(256)
void combine_kernel(float* __restrict__ out) {
    const int t = blockIdx.x;
    const uint32_t s0 = d_slotEP[t * 2 + 0];
    const uint32_t s1 = d_slotEP[t * 2 + 1];
    const int e0 = (int)(s0 >> 20), p0 = (int)(s0 & 0xFFFFFu);
    const int e1 = (int)(s1 >> 20), p1 = (int)(s1 & 0xFFFFFu);
    const float w0 = d_wtok[t * 2 + 0];
    const float w1 = d_wtok[t * 2 + 1];
    const size_t r0 = (size_t)(expert_offset(e0) + p0) * HH;
    const size_t r1 = (size_t)(expert_offset(e1) + p1) * HH;
    const float4* a = (const float4*)(d_osc + r0);
    const float4* b = (const float4*)(d_osc + r1);
    float4* o = (float4*)(out + (size_t)t * HH);
    const int k = threadIdx.x;           // 256 threads x float4 = 1024
    float4 va = a[k], vb = b[k];
    float4 vo;
    vo.x = w0 * va.x + w1 * vb.x;
    vo.y = w0 * va.y + w1 * vb.y;
    vo.z = w0 * va.z + w1 * vb.z;
    vo.w = w0 * va.w + w1 * vb.w;
    o[k] = vo;
}

// ---------------- launch ----------------
extern "C" void kernel_launch(void* const* d_in, const int* in_sizes, int n_in,
                              void* d_out, int out_size) {
    const float* x  = (const float*)d_in[0];   // [T,H]
    const float* Wg = (const float*)d_in[1];   // [E,H]
    const float* W1 = (const float*)d_in[2];   // [E,I,H]
    const float* b1 = (const float*)d_in[3];   // [E,I]
    const float* W2 = (const float*)d_in[4];   // [E,H,I]
    const float* b2 = (const float*)d_in[5];   // [E,H]
    float* out = (float*)d_out;

    float* logits = nullptr;
    if ((size_t)out_size >= (size_t)TT * HH + (size_t)TT * EE)
        logits = out + (size_t)TT * HH;

    cudaFuncSetAttribute(moe_gemm_kernel<true>,  cudaFuncAttributeMaxDynamicSharedMemorySize, SMEM_DYN);
    cudaFuncSetAttribute(moe_gemm_kernel<false>, cudaFuncAttributeMaxDynamicSharedMemorySize, SMEM_DYN);

    cvt_f16_kernel<<<4096, 256>>>((const float4*)W1, 1, (size_t)EE * II * HH / 4);  // zeroes counts
    cvt_f16_kernel<<<4096, 256>>>((const float4*)W2, 2, (size_t)EE * HH * II / 4);
    router_kernel<<<TT / 8, 256>>>(x, Wg, logits);   // also writes d_xh + slots

    dim3 g1(II / BN, TT / BM, EE);   // (32, 128, 8) -- 4th launch: ncu profiles this
    moe_gemm_kernel<true><<<g1, NT, SMEM_DYN>>>(b1);

    dim3 g2(HH / BN, TT / BM, EE);   // (8, 128, 8)
    moe_gemm_kernel<false><<<g2, NT, SMEM_DYN>>>(b2);

    combine_kernel<<<TT, 256>>>(out);
}

// round 12
// speedup vs baseline: 2.7268x; 1.0038x over previous
#include <cuda_runtime.h>
#include <cuda_fp16.h>
#include <cstdint>

// Problem constants
#define TT 16384   // B*S tokens
#define HH 1024    // hidden
#define II 4096    // intermediate
#define EE 8       // experts

// ---------------- scratch (device globals; no runtime allocation) ----------
__device__ int      d_counts[EE];
__device__ int      d_tok[EE * TT];
__device__ uint32_t d_slotEP[2 * TT];             // (expert<<20)|pos per token slot
__device__ float    d_wtok[2 * TT];               // per-token top-2 weights
__device__ __half   d_hmid[(size_t)2 * TT * II];  // fp16 intermediate (268 MB)
__device__ float    d_osc[(size_t)2 * TT * HH];   // fp32 expert outputs (134 MB)
__device__ __half   d_xh[(size_t)TT * HH];        // fp16 x (written by router)
__device__ __half   d_w1h[(size_t)EE * II * HH];  // fp16 W1
__device__ __half   d_w2h[(size_t)EE * HH * II];  // fp16 W2

// ---------------- helpers ----------------
__device__ __forceinline__ float silu_f(float v) { return v / (1.0f + __expf(-v)); }
__device__ __forceinline__ uint32_t smem_u32(const void* p) {
    uint32_t a;
    asm("{ .reg .u64 t; cvta.to.shared.u64 t, %1; cvt.u32.u64 %0, t; }" : "=r"(a) : "l"(p));
    return a;
}
__device__ __forceinline__ int expert_offset(int e) {
    int off = 0;
#pragma unroll
    for (int q = 0; q < EE; q++) off += (q < e) ? d_counts[q] : 0;
    return off;
}

#define MMA_F16(D, A, B_)                                                        \
    asm volatile(                                                                \
        "mma.sync.aligned.m16n8k16.row.col.f32.f16.f16.f32 "                     \
        "{%0,%1,%2,%3}, {%4,%5,%6,%7}, {%8,%9}, {%0,%1,%2,%3};\n"                \
        : "+f"((D)[0]), "+f"((D)[1]), "+f"((D)[2]), "+f"((D)[3])                 \
        : "r"((A)[0]), "r"((A)[1]), "r"((A)[2]), "r"((A)[3]),                    \
          "r"((B_)[0]), "r"((B_)[1]))

#define LDSM_X4(r0, r1, r2, r3, addr)                                            \
    asm volatile("ldmatrix.sync.aligned.m8n8.x4.shared.b16 {%0,%1,%2,%3}, [%4];" \
        : "=r"(r0), "=r"(r1), "=r"(r2), "=r"(r3) : "r"(addr))

#define CP_ASYNC16(saddr, gptr) \
    asm volatile("cp.async.cg.shared.global [%0], [%1], 16;" :: "r"(saddr), "l"(gptr) : "memory")
#define CP_COMMIT() asm volatile("cp.async.commit_group;" ::: "memory")
#define CP_WAIT3()  asm volatile("cp.async.wait_group 3;" ::: "memory")

// ---------------- kernel: fp32 -> fp16 weight conversion (+zero counters) --
__global__ __launch_bounds__(256)
void cvt_f16_kernel(const float4* __restrict__ src, int which, size_t n4) {
    if (which == 1 && blockIdx.x == 0 && threadIdx.x < EE)
        d_counts[threadIdx.x] = 0;
    __half* dstb = (which == 1) ? d_w1h : d_w2h;
    uint2* dst = (uint2*)dstb;
    size_t i  = (size_t)blockIdx.x * blockDim.x + threadIdx.x;
    size_t st = (size_t)gridDim.x * blockDim.x;
    for (; i < n4; i += st) {
        float4 v = src[i];
        __half2 h0 = __floats2half2_rn(v.x, v.y);
        __half2 h1 = __floats2half2_rn(v.z, v.w);
        uint2 o;
        o.x = *(uint32_t*)&h0;
        o.y = *(uint32_t*)&h1;
        dst[i] = o;
    }
}

// ---------------- kernel: router (fp32) + fused x->fp16 + slot record ------
__global__ __launch_bounds__(256)
void router_kernel(const float* __restrict__ x,
                   const float* __restrict__ Wg,
                   float* __restrict__ logits_out) {
    __shared__ float sWg[EE][HH];
    for (int i = threadIdx.x; i < EE * HH; i += blockDim.x)
        sWg[i / HH][i % HH] = Wg[i];
    __syncthreads();

    const int warp = threadIdx.x >> 5;
    const int lane = threadIdx.x & 31;
    const int t = blockIdx.x * 8 + warp;
    if (t >= TT) return;

    const float* xr = x + (size_t)t * HH;

    // fused x -> fp16
    {
        uint2* xo = (uint2*)(d_xh + (size_t)t * HH);
        const float4* xi = (const float4*)xr;
        for (int k4 = lane; k4 < HH / 4; k4 += 32) {
            float4 v = xi[k4];
            __half2 h0 = __floats2half2_rn(v.x, v.y);
            __half2 h1 = __floats2half2_rn(v.z, v.w);
            uint2 o;
            o.x = *(uint32_t*)&h0;
            o.y = *(uint32_t*)&h1;
            xo[k4] = o;
        }
    }

    float acc[EE];
#pragma unroll
    for (int e = 0; e < EE; e++) acc[e] = 0.0f;
    for (int k = lane; k < HH; k += 32) {
        float xv = xr[k];
#pragma unroll
        for (int e = 0; e < EE; e++) acc[e] += xv * sWg[e][k];
    }
#pragma unroll
    for (int off = 16; off > 0; off >>= 1)
#pragma unroll
        for (int e = 0; e < EE; e++)
            acc[e] += __shfl_xor_sync(0xFFFFFFFFu, acc[e], off);

    if (lane == 0) {
        if (logits_out)
#pragma unroll
            for (int e = 0; e < EE; e++) logits_out[(size_t)t * EE + e] = acc[e];
        int i0 = 0; float v0 = acc[0];
#pragma unroll
        for (int e = 1; e < EE; e++) if (acc[e] > v0) { v0 = acc[e]; i0 = e; }
        int i1 = -1; float v1 = -3.4e38f;
#pragma unroll
        for (int e = 0; e < EE; e++)
            if (e != i0 && acc[e] > v1) { v1 = acc[e]; i1 = e; }
        float r  = expf(v1 - v0);
        float w0 = 1.0f / (1.0f + r);
        float w1 = 1.0f - w0;
        int p0 = atomicAdd(&d_counts[i0], 1);
        d_tok[i0 * TT + p0] = t;
        int p1 = atomicAdd(&d_counts[i1], 1);
        d_tok[i1 * TT + p1] = t;
        d_slotEP[t * 2 + 0] = ((uint32_t)i0 << 20) | (uint32_t)p0;
        d_slotEP[t * 2 + 1] = ((uint32_t)i1 << 20) | (uint32_t)p1;
        d_wtok[t * 2 + 0] = w0;
        d_wtok[t * 2 + 1] = w1;
    }
}

// ---------------- GEMM: fp16 m16n8k16, 128x128 CTA, 4 warps, 2 CTAs/SM --
// 4 warps (2m x 2n), 64x64 per warp, double-buffered ldmatrix fragments,
// 5-stage cp.async ring, cp.async issues interleaved into the MMA stream.
constexpr int BM = 128, BN = 128, BK = 32;
constexpr int NT = 128;                            // threads per CTA
constexpr int BKW = 20;                            // padded words/row
constexpr int A_STAGE_B = BM * BKW * 4;            // 10240 B
constexpr int B_STAGE_B = BN * BKW * 4;            // 10240 B
constexpr int STAGE_B   = A_STAGE_B + B_STAGE_B;   // 20480 B
constexpr int NSTAGE    = 5;
constexpr int SMEM_DYN  = NSTAGE * STAGE_B;        // 102400 B (2 CTAs -> 200 KB/SM)

__device__ __forceinline__ void load_frags(uint32_t af[4][4], uint32_t bf[8][2],
                                           const uint32_t aLd[4], const uint32_t bLd[4],
                                           uint32_t ko) {
#pragma unroll
    for (int mf = 0; mf < 4; mf++)
        LDSM_X4(af[mf][0], af[mf][1], af[mf][2], af[mf][3], aLd[mf] + ko);
#pragma unroll
    for (int j = 0; j < 4; j++)
        LDSM_X4(bf[2 * j][0], bf[2 * j][1], bf[2 * j + 1][0], bf[2 * j + 1][1],
                bLd[j] + ko);
}

__device__ __forceinline__ void mma_all(float acc[4][8][4],
                                        const uint32_t af[4][4],
                                        const uint32_t bf[8][2]) {
#pragma unroll
    for (int mf = 0; mf < 4; mf++)
#pragma unroll
        for (int nf = 0; nf < 8; nf++)
            MMA_F16(acc[mf][nf], af[mf], bf[nf]);
}

template <bool FIRST>
__global__ __launch_bounds__(NT, 2)
void moe_gemm_kernel(const float* __restrict__ bias) {
    const int e   = blockIdx.z;
    const int cnt = d_counts[e];
    const int m0  = blockIdx.y * BM;
    if (m0 >= cnt) return;
    const int n0   = blockIdx.x * BN;
    const int KDIM = FIRST ? HH : II;
    const int NDIM = FIRST ? II : HH;
    const int offs = expert_offset(e);
    const int NC   = KDIM / BK;

    extern __shared__ char dynsmem[];
    const uint32_t sbase = smem_u32(dynsmem);

    const int tid = threadIdx.x;
    const __half* Aglob = FIRST ? d_xh : d_hmid;
    const __half* Wt    = FIRST ? d_w1h : d_w2h;

    // cp.async loaders: A 4 chunks/thread, B 4 chunks/thread (16B each)
    const __half* aG[4]; uint32_t aSoff[4];
#pragma unroll
    for (int j = 0; j < 4; j++) {
        int idx = tid + j * NT;
        int row = idx >> 2, c = idx & 3;
        int gm = m0 + row;
        if (gm >= cnt) gm = cnt - 1;
        size_t rowoff;
        if (FIRST) rowoff = (size_t)d_tok[e * TT + gm] * HH;
        else       rowoff = (size_t)(offs + gm) * II;
        aG[j]    = Aglob + rowoff + c * 8;
        aSoff[j] = row * (BKW * 4) + c * 16;
    }
    const __half* bG[4]; uint32_t bSoff[4];
#pragma unroll
    for (int j = 0; j < 4; j++) {
        int idx = tid + j * NT;
        int row = idx >> 2, c = idx & 3;
        bG[j]    = Wt + (size_t)e * ((size_t)II * HH) + (size_t)(n0 + row) * KDIM + c * 8;
        bSoff[j] = A_STAGE_B + row * (BKW * 4) + c * 16;
    }

    // prologue: stages 0..3
#pragma unroll
    for (int s = 0; s < NSTAGE - 1; s++) {
        uint32_t so = sbase + s * STAGE_B;
#pragma unroll
        for (int j = 0; j < 4; j++) CP_ASYNC16(so + aSoff[j], aG[j] + s * BK);
#pragma unroll
        for (int j = 0; j < 4; j++) CP_ASYNC16(so + bSoff[j], bG[j] + s * BK);
        CP_COMMIT();
    }

    const int wid = tid >> 5, lane = tid & 31;
    const int wm = (wid >> 1) * 64;       // 2 m-warps
    const int wn = (wid & 1) * 64;        // 2 n-warps
    const int g = lane >> 2, tg = lane & 3;

    // ldmatrix per-lane base addresses
    uint32_t aLd[4];
#pragma unroll
    for (int mf = 0; mf < 4; mf++) {
        int row = wm + mf * 16 + (lane & 7) + ((lane >> 3) & 1) * 8;
        int col = ((lane >> 4) & 1) * 16;
        aLd[mf] = sbase + row * (BKW * 4) + col;
    }
    uint32_t bLd[4];
#pragma unroll
    for (int nf2 = 0; nf2 < 4; nf2++) {
        int row = wn + nf2 * 16 + (lane & 7) + ((lane >> 4) & 1) * 8;
        int col = ((lane >> 3) & 1) * 16;
        bLd[nf2] = sbase + A_STAGE_B + row * (BKW * 4) + col;
    }

    float acc[4][8][4];
#pragma unroll
    for (int a = 0; a < 4; a++)
#pragma unroll
        for (int b = 0; b < 8; b++)
#pragma unroll
            for (int c = 0; c < 4; c++) acc[a][b][c] = 0.0f;

    // software-pipelined fragments: cur = kk0 of chunk i, nxt = kk1
    uint32_t afc[4][4], bfc[8][2], afn[4][4], bfn[8][2];

    CP_WAIT3();
    __syncthreads();
    load_frags(afc, bfc, aLd, bLd, 0u);        // chunk 0, kk0

    int stage = 0;
    for (int i = 0; i < NC; i++) {
        const uint32_t stoff = stage * STAGE_B;

        load_frags(afn, bfn, aLd, bLd, stoff + 32);   // kk1 of chunk i

        // kk0 MMAs with the 8 cp.async issues (chunk i+4) interleaved
        const int  nx = i + NSTAGE - 1;
        const bool pf = nx < NC;
        const int  ps = (stage == 0) ? NSTAGE - 1 : stage - 1;   // (i+4) mod 5
        const uint32_t so = sbase + ps * STAGE_B;
#pragma unroll
        for (int mf = 0; mf < 4; mf++) {
#pragma unroll
            for (int nf = 0; nf < 8; nf++) {
                MMA_F16(acc[mf][nf], afc[mf], bfc[nf]);
                if (nf == 3 && pf) CP_ASYNC16(so + aSoff[mf], aG[mf] + nx * BK);
                if (nf == 7 && pf) CP_ASYNC16(so + bSoff[mf], bG[mf] + nx * BK);
            }
        }
        CP_COMMIT();

        const int nstage = (stage + 1 == NSTAGE) ? 0 : stage + 1;
        if (i + 1 < NC) {
            CP_WAIT3();
            __syncthreads();
            load_frags(afc, bfc, aLd, bLd, nstage * STAGE_B);
        }
        mma_all(acc, afn, bfn);                       // kk1 of chunk i
        stage = nstage;
    }

    // epilogue (acc: d0,d1 = row g cols 2tg,2tg+1; d2,d3 = row g+8)
#pragma unroll
    for (int mf = 0; mf < 4; mf++) {
#pragma unroll
        for (int half = 0; half < 2; half++) {
            int m = m0 + wm + mf * 16 + g + half * 8;
            if (m >= cnt) continue;
            if (FIRST) {
                __half* dst = d_hmid + (size_t)(offs + m) * II + n0;
#pragma unroll
                for (int nf = 0; nf < 8; nf++) {
                    int col = wn + nf * 8 + tg * 2;
                    float bb0 = bias[(size_t)e * NDIM + n0 + col];
                    float bb1 = bias[(size_t)e * NDIM + n0 + col + 1];
                    float s0 = silu_f(acc[mf][nf][half * 2 + 0] + bb0);
                    float s1 = silu_f(acc[mf][nf][half * 2 + 1] + bb1);
                    *(__half2*)(dst + col) = __floats2half2_rn(s0, s1);
                }
            } else {
                float* dst = d_osc + (size_t)(offs + m) * HH + n0;
#pragma unroll
                for (int nf = 0; nf < 8; nf++) {
                    int col = wn + nf * 8 + tg * 2;
                    float bb0 = bias[(size_t)e * NDIM + n0 + col];
                    float bb1 = bias[(size_t)e * NDIM + n0 + col + 1];
                    *(float2*)(dst + col) = make_float2(acc[mf][nf][half * 2 + 0] + bb0,
                                                        acc[mf][nf][half * 2 + 1] + bb1);
                }
            }
        }
    }
}

// ---------------- kernel: combine two expert rows per token ----------------
__global__ __launch_bounds__(256)
void combine_kernel(float* __restrict__ out) {
    const int t = blockIdx.x;
    const uint32_t s0 = d_slotEP[t * 2 + 0];
    const uint32_t s1 = d_slotEP[t * 2 + 1];
    const int e0 = (int)(s0 >> 20), p0 = (int)(s0 & 0xFFFFFu);
    const int e1 = (int)(s1 >> 20), p1 = (int)(s1 & 0xFFFFFu);
    const float w0 = d_wtok[t * 2 + 0];
    const float w1 = d_wtok[t * 2 + 1];
    const size_t r0 = (size_t)(expert_offset(e0) + p0) * HH;
    const size_t r1 = (size_t)(expert_offset(e1) + p1) * HH;
    const float4* a = (const float4*)(d_osc + r0);
    const float4* b = (const float4*)(d_osc + r1);
    float4* o = (float4*)(out + (size_t)t * HH);
    const int k = threadIdx.x;           // 256 threads x float4 = 1024
    float4 va = a[k], vb = b[k];
    float4 vo;
    vo.x = w0 * va.x + w1 * vb.x;
    vo.y = w0 * va.y + w1 * vb.y;
    vo.z = w0 * va.z + w1 * vb.z;
    vo.w = w0 * va.w + w1 * vb.w;
    o[k] = vo;
}

// ---------------- launch ----------------
extern "C" void kernel_launch(void* const* d_in, const int* in_sizes, int n_in,
                              void* d_out, int out_size) {
    const float* x  = (const float*)d_in[0];   // [T,H]
    const float* Wg = (const float*)d_in[1];   // [E,H]
    const float* W1 = (const float*)d_in[2];   // [E,I,H]
    const float* b1 = (const float*)d_in[3];   // [E,I]
    const float* W2 = (const float*)d_in[4];   // [E,H,I]
    const float* b2 = (const float*)d_in[5];   // [E,H]
    float* out = (float*)d_out;

    float* logits = nullptr;
    if ((size_t)out_size >= (size_t)TT * HH + (size_t)TT * EE)
        logits = out + (size_t)TT * HH;

    cudaFuncSetAttribute(moe_gemm_kernel<true>,  cudaFuncAttributeMaxDynamicSharedMemorySize, SMEM_DYN);
    cudaFuncSetAttribute(moe_gemm_kernel<false>, cudaFuncAttributeMaxDynamicSharedMemorySize, SMEM_DYN);

    cvt_f16_kernel<<<4096, 256>>>((const float4*)W1, 1, (size_t)EE * II * HH / 4);  // zeroes counts
    cvt_f16_kernel<<<4096, 256>>>((const float4*)W2, 2, (size_t)EE * HH * II / 4);
    router_kernel<<<TT / 8, 256>>>(x, Wg, logits);   // also writes d_xh + slots

    dim3 g1(II / BN, TT / BM, EE);   // (32, 128, 8) -- 4th launch: ncu profiles this
    moe_gemm_kernel<true><<<g1, NT, SMEM_DYN>>>(b1);

    dim3 g2(HH / BN, TT / BM, EE);   // (8, 128, 8)
    moe_gemm_kernel<false><<<g2, NT, SMEM_DYN>>>(b2);

    combine_kernel<<<TT, 256>>>(out);
}